// round 4
// baseline (speedup 1.0000x reference)
#include <cuda_runtime.h>
#include <cuda_bf16.h>
#include <math.h>

// ---------------------------------------------------------------------------
// Swin Transformer block, fp32.
// B=32, H=W=56, C=192, NH=6, WS=7, SS=3, HD=32, N=49, MLP_H=768
// tokens per image L=3136, total tokens TOT=100352, windows per image 64,
// total windows B_=2048.
// ---------------------------------------------------------------------------

#define Bn     32
#define Hh     56
#define Ww     56
#define Cc     192
#define NHh    6
#define WSs    7
#define SSs    3
#define HDd    32
#define Nn     49
#define MLPH   768
#define Ltok   (Hh*Ww)            // 3136
#define TOT    (Bn*Ltok)          // 100352
#define NWIN   2048               // B * 64
#define SCALEF 0.17677669529663687f  // 32^-0.5

// ------------------------- scratch (device globals) ------------------------
__device__ float g_XW [TOT * Cc];     // LN1 + shifted/windowed tokens   77MB
__device__ float g_QKV[TOT * 3 * Cc]; // qkv                            231MB
__device__ float g_ATT[TOT * Cc];     // attention output (window order) 77MB
__device__ float g_XR [TOT * Cc];     // x + attn (token order)          77MB
__device__ float g_XN2[TOT * Cc];     // LN2(xr)                         77MB
__device__ float g_H  [TOT * MLPH];   // gelu(fc1)                      308MB

// --------------------- token <-> (shifted window) mapping ------------------
// window-order token t -> source/dest row in [B, 56*56] token order.
__device__ __forceinline__ int win_to_tok(int t) {
    int win = t / Nn, r = t - win * Nn;
    int b = win >> 6, w_ = win & 63;
    int wh = w_ >> 3, ww = w_ & 7;
    int ih = r / WSs, iw = r - ih * WSs;
    int rr = wh * WSs + ih + SSs; if (rr >= Hh) rr -= Hh;
    int cc = ww * WSs + iw + SSs; if (cc >= Ww) cc -= Ww;
    return b * Ltok + rr * Ww + cc;
}

// --------------------------- LN kernels -------------------------------------
// one warp per token; 6 elems per lane (C=192)
__global__ void ln1_gather_kernel(const float* __restrict__ x,
                                  const float* __restrict__ g,
                                  const float* __restrict__ bt) {
    int warp = (blockIdx.x * blockDim.x + threadIdx.x) >> 5;
    int lane = threadIdx.x & 31;
    if (warp >= TOT) return;
    const float* src = x + (size_t)win_to_tok(warp) * Cc;
    float v[6], s = 0.f, ss = 0.f;
#pragma unroll
    for (int k = 0; k < 6; k++) { v[k] = src[lane + k * 32]; s += v[k]; ss += v[k] * v[k]; }
#pragma unroll
    for (int o = 16; o; o >>= 1) {
        s  += __shfl_xor_sync(0xffffffffu, s, o);
        ss += __shfl_xor_sync(0xffffffffu, ss, o);
    }
    float mu = s * (1.f / Cc);
    float rstd = rsqrtf(ss * (1.f / Cc) - mu * mu + 1e-5f);
    float* dst = g_XW + (size_t)warp * Cc;
#pragma unroll
    for (int k = 0; k < 6; k++) {
        int c = lane + k * 32;
        dst[c] = (v[k] - mu) * rstd * g[c] + bt[c];
    }
}

__global__ void ln2_kernel(const float* __restrict__ g,
                           const float* __restrict__ bt) {
    int warp = (blockIdx.x * blockDim.x + threadIdx.x) >> 5;
    int lane = threadIdx.x & 31;
    if (warp >= TOT) return;
    const float* src = g_XR + (size_t)warp * Cc;
    float v[6], s = 0.f, ss = 0.f;
#pragma unroll
    for (int k = 0; k < 6; k++) { v[k] = src[lane + k * 32]; s += v[k]; ss += v[k] * v[k]; }
#pragma unroll
    for (int o = 16; o; o >>= 1) {
        s  += __shfl_xor_sync(0xffffffffu, s, o);
        ss += __shfl_xor_sync(0xffffffffu, ss, o);
    }
    float mu = s * (1.f / Cc);
    float rstd = rsqrtf(ss * (1.f / Cc) - mu * mu + 1e-5f);
    float* dst = g_XN2 + (size_t)warp * Cc;
#pragma unroll
    for (int k = 0; k < 6; k++) {
        int c = lane + k * 32;
        dst[c] = (v[k] - mu) * rstd * g[c] + bt[c];
    }
}

// --------------------------- SGEMM 64x64x16 ---------------------------------
// C[M,Nd] = A[M,K] * Bw[Nd,K]^T  (weights row-major [out,in]), fused epilogues.
// 256 threads, 4x4 per thread. M % 64 == 0, Nd % 64 == 0, K % 16 == 0.
// EPI: 0 plain store, 1 proj (bias + scatter + residual(x) -> XR),
//      2 bias + exact gelu, 3 bias + residual(XR) -> out
template <int EPI>
__global__ __launch_bounds__(256)
void sgemm64(const float* __restrict__ A, const float* __restrict__ Bw,
             const float* __restrict__ bias, const float* __restrict__ res,
             float* __restrict__ C, int Nd, int K) {
    __shared__ float As[16][64];
    __shared__ float Bs[16][64];
    int tid = threadIdx.x;
    int rowBase = blockIdx.y * 64;
    int nBase   = blockIdx.x * 64;
    int lm  = tid >> 2;          // 0..63
    int lk4 = (tid & 3) * 4;     // 0,4,8,12
    const float* Ag = A  + (size_t)(rowBase + lm) * K + lk4;
    const float* Bg = Bw + (size_t)(nBase   + lm) * K + lk4;
    int tx = tid & 15, ty = tid >> 4;

    float acc[4][4];
#pragma unroll
    for (int i = 0; i < 4; i++)
#pragma unroll
        for (int j = 0; j < 4; j++) acc[i][j] = 0.f;

    for (int kt = 0; kt < K; kt += 16) {
        float4 av = *(const float4*)(Ag + kt);
        float4 bv = *(const float4*)(Bg + kt);
        __syncthreads();
        As[lk4 + 0][lm] = av.x; As[lk4 + 1][lm] = av.y;
        As[lk4 + 2][lm] = av.z; As[lk4 + 3][lm] = av.w;
        Bs[lk4 + 0][lm] = bv.x; Bs[lk4 + 1][lm] = bv.y;
        Bs[lk4 + 2][lm] = bv.z; Bs[lk4 + 3][lm] = bv.w;
        __syncthreads();
#pragma unroll
        for (int k2 = 0; k2 < 16; k2++) {
            float4 a = *(const float4*)&As[k2][ty * 4];
            float4 b = *(const float4*)&Bs[k2][tx * 4];
            float am[4] = {a.x, a.y, a.z, a.w};
            float bn[4] = {b.x, b.y, b.z, b.w};
#pragma unroll
            for (int i = 0; i < 4; i++)
#pragma unroll
                for (int j = 0; j < 4; j++) acc[i][j] += am[i] * bn[j];
        }
    }

#pragma unroll
    for (int i = 0; i < 4; i++) {
        int row = rowBase + ty * 4 + i;
        if (EPI == 1) {
            int dst = win_to_tok(row);
            const float* rres = res + (size_t)dst * Nd;
            float* rout = C + (size_t)dst * Nd;
#pragma unroll
            for (int j = 0; j < 4; j++) {
                int col = nBase + tx * 4 + j;
                rout[col] = rres[col] + acc[i][j] + bias[col];
            }
        } else {
            float* rout = C + (size_t)row * Nd;
#pragma unroll
            for (int j = 0; j < 4; j++) {
                int col = nBase + tx * 4 + j;
                float v = acc[i][j];
                if (EPI == 0) {
                    rout[col] = v;
                } else if (EPI == 2) {
                    v += bias[col];
                    rout[col] = 0.5f * v * (1.0f + erff(v * 0.70710678118654752f));
                } else { // EPI == 3
                    rout[col] = res[(size_t)row * Nd + col] + v + bias[col];
                }
            }
        }
    }
}

// --------------------------- attention --------------------------------------
// grid (NH, NWIN), 64 threads. rel-pos index and shifted-window mask computed
// analytically.
__device__ __forceinline__ int region_label(int R, int Cg) {
    int lr = (R  < Hh - WSs) ? 0 : ((R  < Hh - SSs) ? 1 : 2);
    int lc = (Cg < Ww - WSs) ? 0 : ((Cg < Ww - SSs) ? 1 : 2);
    return lr * 3 + lc;
}

__global__ __launch_bounds__(64)
void attn_kernel(const float* __restrict__ bias_table) {
    int h   = blockIdx.x;
    int win = blockIdx.y;
    __shared__ float ks[Nn][HDd];
    __shared__ float vs[Nn][HDd];
    int tid = threadIdx.x;
    const float* base = g_QKV + (size_t)win * Nn * (3 * Cc);

    for (int idx = tid; idx < Nn * HDd; idx += 64) {
        int j = idx >> 5, d = idx & 31;
        ks[j][d] = base[j * (3 * Cc) + Cc     + h * HDd + d];
        vs[j][d] = base[j * (3 * Cc) + 2 * Cc + h * HDd + d];
    }
    __syncthreads();

    if (tid < Nn) {
        int ih = tid / WSs, iw = tid - ih * WSs;
        int wh = (win & 63) >> 3, ww = win & 7;
        int li = region_label(wh * WSs + ih, ww * WSs + iw);

        float q[HDd];
#pragma unroll
        for (int d = 0; d < HDd; d++)
            q[d] = base[tid * (3 * Cc) + h * HDd + d] * SCALEF;

        float sarr[Nn];
        float mx = -1e30f;
        for (int j = 0; j < Nn; j++) {
            int jh = j / WSs, jw = j - jh * WSs;
            int lj = region_label(wh * WSs + jh, ww * WSs + jw);
            int ridx = (ih - jh + WSs - 1) * (2 * WSs - 1) + (iw - jw + WSs - 1);
            float s = bias_table[ridx * NHh + h] + ((li != lj) ? -100.f : 0.f);
#pragma unroll
            for (int d = 0; d < HDd; d++) s += q[d] * ks[j][d];
            sarr[j] = s;
            mx = fmaxf(mx, s);
        }
        float sum = 0.f;
        for (int j = 0; j < Nn; j++) { sarr[j] = expf(sarr[j] - mx); sum += sarr[j]; }
        float inv = 1.f / sum;

        float oacc[HDd];
#pragma unroll
        for (int d = 0; d < HDd; d++) oacc[d] = 0.f;
        for (int j = 0; j < Nn; j++) {
            float p = sarr[j] * inv;
#pragma unroll
            for (int d = 0; d < HDd; d++) oacc[d] += p * vs[j][d];
        }
        float* o = g_ATT + ((size_t)(win * Nn + tid)) * Cc + h * HDd;
#pragma unroll
        for (int d = 0; d < HDd; d++) o[d] = oacc[d];
    }
}

// --------------------------- launch ------------------------------------------
extern "C" void kernel_launch(void* const* d_in, const int* in_sizes, int n_in,
                              void* d_out, int out_size) {
    const float* x        = (const float*)d_in[0];
    const float* norm1_g  = (const float*)d_in[1];
    const float* norm1_b  = (const float*)d_in[2];
    const float* qkv_w    = (const float*)d_in[3];   // [576,192]
    const float* rel_bias = (const float*)d_in[4];   // [169,6]
    const float* proj_w   = (const float*)d_in[5];   // [192,192]
    const float* proj_b   = (const float*)d_in[6];
    const float* norm2_g  = (const float*)d_in[7];
    const float* norm2_b  = (const float*)d_in[8];
    const float* fc1_w    = (const float*)d_in[9];   // [768,192]
    const float* fc1_b    = (const float*)d_in[10];
    const float* fc2_w    = (const float*)d_in[11];  // [192,768]
    const float* fc2_b    = (const float*)d_in[12];
    float* out = (float*)d_out;

    float *XW, *QKV, *ATT, *XR, *XN2, *Hb;
    cudaGetSymbolAddress((void**)&XW,  g_XW);
    cudaGetSymbolAddress((void**)&QKV, g_QKV);
    cudaGetSymbolAddress((void**)&ATT, g_ATT);
    cudaGetSymbolAddress((void**)&XR,  g_XR);
    cudaGetSymbolAddress((void**)&XN2, g_XN2);
    cudaGetSymbolAddress((void**)&Hb,  g_H);

    // 1. LN1 + cyclic shift + window partition  -> XW (window token order)
    ln1_gather_kernel<<<TOT / 8, 256>>>(x, norm1_g, norm1_b);
    // 2. QKV gemm: [100352,192] x [576,192]^T -> QKV
    sgemm64<0><<<dim3(576 / 64, TOT / 64), 256>>>(XW, qkv_w, nullptr, nullptr,
                                                  QKV, 3 * Cc, Cc);
    // 3. windowed attention (bias + shifted mask + softmax + @V) -> ATT
    attn_kernel<<<dim3(NHh, NWIN), 64>>>(rel_bias);
    // 4. proj gemm + bias + window-reverse/unshift scatter + residual -> XR
    sgemm64<1><<<dim3(Cc / 64, TOT / 64), 256>>>(ATT, proj_w, proj_b, x,
                                                 XR, Cc, Cc);
    // 5. LN2 -> XN2
    ln2_kernel<<<TOT / 8, 256>>>(norm2_g, norm2_b);
    // 6. FC1 + bias + exact GELU -> H
    sgemm64<2><<<dim3(MLPH / 64, TOT / 64), 256>>>(XN2, fc1_w, fc1_b, nullptr,
                                                   Hb, MLPH, Cc);
    // 7. FC2 + bias + residual(XR) -> out
    sgemm64<3><<<dim3(Cc / 64, TOT / 64), 256>>>(Hb, fc2_w, fc2_b, XR,
                                                 out, Cc, MLPH);
}

// round 6
// speedup vs baseline: 2.2423x; 2.2423x over previous
#include <cuda_runtime.h>
#include <cuda_bf16.h>
#include <math.h>
#include <stdint.h>

// ---------------------------------------------------------------------------
// Swin block: B=32,H=W=56,C=192,NH=6,WS=7,SS=3,HD=32,N=49,MLP_H=768
// GEMMs via mma.sync tf32 (portable sm_80+ path; sm_100 plain target).
// ---------------------------------------------------------------------------

#define Bn     32
#define Hh     56
#define Ww     56
#define Cc     192
#define NHh    6
#define WSs    7
#define SSs    3
#define HDd    32
#define Nn     49
#define MLPH   768
#define Ltok   (Hh*Ww)
#define TOT    (Bn*Ltok)          // 100352
#define NWIN   2048
#define SCALEF 0.17677669529663687f

// GEMM tiling
#define BM   256
#define BN   64
#define BK   32
#define PAD  36                   // smem row pitch in floats (bank-conflict-free)
#define ABUF (BM*PAD)             // floats per A buffer
#define BBUF (BN*PAD)
#define SMEM_BYTES ((2*ABUF + 2*BBUF) * 4)   // 92160

// ------------------------- scratch (device globals) ------------------------
__device__ float g_XW [TOT * Cc];
__device__ float g_QKV[TOT * 3 * Cc];
__device__ float g_ATT[TOT * Cc];
__device__ float g_XR [TOT * Cc];
__device__ float g_XN2[TOT * Cc];
__device__ float g_H  [TOT * MLPH];

// --------------------------- PTX helpers -----------------------------------
__device__ __forceinline__ uint32_t smem_u32(const void* p) {
    uint32_t a;
    asm("{ .reg .u64 t; cvta.to.shared.u64 t, %1; cvt.u32.u64 %0, t; }"
        : "=r"(a) : "l"(p));
    return a;
}

#define CP_ASYNC16(dst, src) \
    asm volatile("cp.async.cg.shared.global [%0], [%1], 16;" :: "r"(dst), "l"(src))
#define CP_COMMIT() asm volatile("cp.async.commit_group;")
#define CP_WAIT(n)  asm volatile("cp.async.wait_group %0;" :: "n"(n))

__device__ __forceinline__ uint32_t f2tf32(float f) {
    uint32_t u;
    asm("cvt.rna.tf32.f32 %0, %1;" : "=r"(u) : "f"(f));
    return u;
}

__device__ __forceinline__ void mma_tf32(float* c, const uint32_t* a, const uint32_t* b) {
    asm volatile(
        "mma.sync.aligned.m16n8k8.row.col.f32.tf32.tf32.f32 "
        "{%0,%1,%2,%3}, {%4,%5,%6,%7}, {%8,%9}, {%0,%1,%2,%3};"
        : "+f"(c[0]), "+f"(c[1]), "+f"(c[2]), "+f"(c[3])
        : "r"(a[0]), "r"(a[1]), "r"(a[2]), "r"(a[3]), "r"(b[0]), "r"(b[1]));
}

// --------------------- token <-> (shifted window) mapping ------------------
__device__ __forceinline__ int win_to_tok(int t) {
    int win = t / Nn, r = t - win * Nn;
    int b = win >> 6, w_ = win & 63;
    int wh = w_ >> 3, ww = w_ & 7;
    int ih = r / WSs, iw = r - ih * WSs;
    int rr = wh * WSs + ih + SSs; if (rr >= Hh) rr -= Hh;
    int cc = ww * WSs + iw + SSs; if (cc >= Ww) cc -= Ww;
    return b * Ltok + rr * Ww + cc;
}

// --------------------------- LN kernels -------------------------------------
__global__ void ln1_gather_kernel(const float* __restrict__ x,
                                  const float* __restrict__ g,
                                  const float* __restrict__ bt) {
    int warp = (blockIdx.x * blockDim.x + threadIdx.x) >> 5;
    int lane = threadIdx.x & 31;
    if (warp >= TOT) return;
    const float* src = x + (size_t)win_to_tok(warp) * Cc;
    float v[6], s = 0.f, ss = 0.f;
#pragma unroll
    for (int k = 0; k < 6; k++) { v[k] = src[lane + k * 32]; s += v[k]; ss += v[k] * v[k]; }
#pragma unroll
    for (int o = 16; o; o >>= 1) {
        s  += __shfl_xor_sync(0xffffffffu, s, o);
        ss += __shfl_xor_sync(0xffffffffu, ss, o);
    }
    float mu = s * (1.f / Cc);
    float rstd = rsqrtf(ss * (1.f / Cc) - mu * mu + 1e-5f);
    float* dst = g_XW + (size_t)warp * Cc;
#pragma unroll
    for (int k = 0; k < 6; k++) {
        int c = lane + k * 32;
        dst[c] = (v[k] - mu) * rstd * g[c] + bt[c];
    }
}

__global__ void ln2_kernel(const float* __restrict__ g,
                           const float* __restrict__ bt) {
    int warp = (blockIdx.x * blockDim.x + threadIdx.x) >> 5;
    int lane = threadIdx.x & 31;
    if (warp >= TOT) return;
    const float* src = g_XR + (size_t)warp * Cc;
    float v[6], s = 0.f, ss = 0.f;
#pragma unroll
    for (int k = 0; k < 6; k++) { v[k] = src[lane + k * 32]; s += v[k]; ss += v[k] * v[k]; }
#pragma unroll
    for (int o = 16; o; o >>= 1) {
        s  += __shfl_xor_sync(0xffffffffu, s, o);
        ss += __shfl_xor_sync(0xffffffffu, ss, o);
    }
    float mu = s * (1.f / Cc);
    float rstd = rsqrtf(ss * (1.f / Cc) - mu * mu + 1e-5f);
    float* dst = g_XN2 + (size_t)warp * Cc;
#pragma unroll
    for (int k = 0; k < 6; k++) {
        int c = lane + k * 32;
        dst[c] = (v[k] - mu) * rstd * g[c] + bt[c];
    }
}

// --------------------------- tf32 mma GEMM ----------------------------------
// C[M,Nd] = A[M,KK] * W[Nd,KK]^T.  CTA tile 256x64, K-chunk 32, cp.async
// double-buffered.  8 warps: 4(M) x 2(N), warp tile 64x32 (4x4 m16n8 frags).
// EPI: 0 plain, 1 proj(bias+scatter+residual->XR), 2 bias+gelu, 3 bias+residual.
template <int EPI, int KK>
__global__ __launch_bounds__(256)
void gemm_mma(const float* __restrict__ A, const float* __restrict__ W,
              const float* __restrict__ bias, const float* __restrict__ res,
              float* __restrict__ outp, int Nd) {
    constexpr int NC = KK / BK;
    extern __shared__ float smem[];
    float* As[2] = {smem, smem + ABUF};
    float* Bs[2] = {smem + 2 * ABUF, smem + 2 * ABUF + BBUF};
    const uint32_t as_u[2] = {smem_u32(As[0]), smem_u32(As[1])};
    const uint32_t bs_u[2] = {smem_u32(Bs[0]), smem_u32(Bs[1])};

    const int tid = threadIdx.x;
    const int wid = tid >> 5;
    const int lane = tid & 31;
    const int gr = lane >> 2, gc = lane & 3;
    const int wm = wid >> 1;          // 0..3  (M position)
    const int wn = wid & 1;           // 0..1  (N position)
    const int mbase = blockIdx.x * BM;
    const int nbase = blockIdx.y * BN;

    const float* Ab = A + (size_t)mbase * KK;
    const float* Wb = W + (size_t)nbase * KK;

    float acc[4][4][4];
#pragma unroll
    for (int i = 0; i < 4; i++)
#pragma unroll
        for (int j = 0; j < 4; j++)
#pragma unroll
            for (int k = 0; k < 4; k++) acc[i][j][k] = 0.f;

    // prologue: load chunk 0
    {
#pragma unroll
        for (int i = tid; i < BM * 8; i += 256) {
            int row = i >> 3, seg = i & 7;
            CP_ASYNC16(as_u[0] + (uint32_t)(row * PAD + seg * 4) * 4,
                       Ab + (size_t)row * KK + seg * 4);
        }
#pragma unroll
        for (int i = tid; i < BN * 8; i += 256) {
            int row = i >> 3, seg = i & 7;
            CP_ASYNC16(bs_u[0] + (uint32_t)(row * PAD + seg * 4) * 4,
                       Wb + (size_t)row * KK + seg * 4);
        }
        CP_COMMIT();
    }

    for (int c = 0; c < NC; ++c) {
        if (c + 1 < NC) {
            const int nb = (c + 1) & 1;
            const int ko = (c + 1) * BK;
#pragma unroll
            for (int i = tid; i < BM * 8; i += 256) {
                int row = i >> 3, seg = i & 7;
                CP_ASYNC16(as_u[nb] + (uint32_t)(row * PAD + seg * 4) * 4,
                           Ab + (size_t)row * KK + ko + seg * 4);
            }
#pragma unroll
            for (int i = tid; i < BN * 8; i += 256) {
                int row = i >> 3, seg = i & 7;
                CP_ASYNC16(bs_u[nb] + (uint32_t)(row * PAD + seg * 4) * 4,
                           Wb + (size_t)row * KK + ko + seg * 4);
            }
            CP_COMMIT();
            CP_WAIT(1);
        } else {
            CP_WAIT(0);
        }
        __syncthreads();

        const float* Asb = As[c & 1];
        const float* Bsb = Bs[c & 1];
#pragma unroll
        for (int ks = 0; ks < 4; ++ks) {
            const int kk = ks * 8;
            uint32_t af[4][4], bf[4][2];
#pragma unroll
            for (int mi = 0; mi < 4; ++mi) {
                int r0 = wm * 64 + mi * 16 + gr;
                af[mi][0] = f2tf32(Asb[r0 * PAD + kk + gc]);
                af[mi][1] = f2tf32(Asb[(r0 + 8) * PAD + kk + gc]);
                af[mi][2] = f2tf32(Asb[r0 * PAD + kk + gc + 4]);
                af[mi][3] = f2tf32(Asb[(r0 + 8) * PAD + kk + gc + 4]);
            }
#pragma unroll
            for (int ni = 0; ni < 4; ++ni) {
                int nr = wn * 32 + ni * 8 + gr;
                bf[ni][0] = f2tf32(Bsb[nr * PAD + kk + gc]);
                bf[ni][1] = f2tf32(Bsb[nr * PAD + kk + gc + 4]);
            }
#pragma unroll
            for (int mi = 0; mi < 4; ++mi)
#pragma unroll
                for (int ni = 0; ni < 4; ++ni)
                    mma_tf32(acc[mi][ni], af[mi], bf[ni]);
        }
        __syncthreads();
    }

    // ----------------------- fused epilogue ---------------------------------
#pragma unroll
    for (int mi = 0; mi < 4; ++mi) {
#pragma unroll
        for (int half = 0; half < 2; ++half) {
            int row = mbase + wm * 64 + mi * 16 + gr + half * 8;
            int orow = row;
            const float* rres = res;
            if (EPI == 1) orow = win_to_tok(row);
#pragma unroll
            for (int ni = 0; ni < 4; ++ni) {
                int col = nbase + wn * 32 + ni * 8 + gc * 2;
                float v0 = acc[mi][ni][half * 2 + 0];
                float v1 = acc[mi][ni][half * 2 + 1];
                float2 o;
                if (EPI == 0) {
                    o = make_float2(v0, v1);
                } else if (EPI == 1) {
                    const float* rp = rres + (size_t)orow * Nd + col;
                    o = make_float2(v0 + bias[col] + rp[0],
                                    v1 + bias[col + 1] + rp[1]);
                } else if (EPI == 2) {
                    float a0 = v0 + bias[col], a1 = v1 + bias[col + 1];
                    const float k = 0.70710678118654752f;
                    o = make_float2(0.5f * a0 * (1.f + erff(a0 * k)),
                                    0.5f * a1 * (1.f + erff(a1 * k)));
                } else {
                    const float* rp = rres + (size_t)row * Nd + col;
                    o = make_float2(v0 + bias[col] + rp[0],
                                    v1 + bias[col + 1] + rp[1]);
                }
                *(float2*)(outp + (size_t)orow * Nd + col) = o;
            }
        }
    }
}

// --------------------------- attention --------------------------------------
__device__ __forceinline__ int region_label(int R, int Cg) {
    int lr = (R  < Hh - WSs) ? 0 : ((R  < Hh - SSs) ? 1 : 2);
    int lc = (Cg < Ww - WSs) ? 0 : ((Cg < Ww - SSs) ? 1 : 2);
    return lr * 3 + lc;
}

__global__ __launch_bounds__(64)
void attn_kernel(const float* __restrict__ bias_table) {
    int h   = blockIdx.x;
    int win = blockIdx.y;
    __shared__ float ks[Nn][HDd];
    __shared__ float vs[Nn][HDd];
    int tid = threadIdx.x;
    const float* base = g_QKV + (size_t)win * Nn * (3 * Cc);

    for (int idx = tid; idx < Nn * HDd; idx += 64) {
        int j = idx >> 5, d = idx & 31;
        ks[j][d] = base[j * (3 * Cc) + Cc     + h * HDd + d];
        vs[j][d] = base[j * (3 * Cc) + 2 * Cc + h * HDd + d];
    }
    __syncthreads();

    if (tid < Nn) {
        int ih = tid / WSs, iw = tid - ih * WSs;
        int wh = (win & 63) >> 3, ww = win & 7;
        int li = region_label(wh * WSs + ih, ww * WSs + iw);

        float q[HDd];
#pragma unroll
        for (int d = 0; d < HDd; d++)
            q[d] = base[tid * (3 * Cc) + h * HDd + d] * SCALEF;

        float sarr[Nn];
        float mx = -1e30f;
        for (int j = 0; j < Nn; j++) {
            int jh = j / WSs, jw = j - jh * WSs;
            int lj = region_label(wh * WSs + jh, ww * WSs + jw);
            int ridx = (ih - jh + WSs - 1) * (2 * WSs - 1) + (iw - jw + WSs - 1);
            float s = bias_table[ridx * NHh + h] + ((li != lj) ? -100.f : 0.f);
#pragma unroll
            for (int d = 0; d < HDd; d++) s += q[d] * ks[j][d];
            sarr[j] = s;
            mx = fmaxf(mx, s);
        }
        float sum = 0.f;
        for (int j = 0; j < Nn; j++) { sarr[j] = expf(sarr[j] - mx); sum += sarr[j]; }
        float inv = 1.f / sum;

        float oacc[HDd];
#pragma unroll
        for (int d = 0; d < HDd; d++) oacc[d] = 0.f;
        for (int j = 0; j < Nn; j++) {
            float p = sarr[j] * inv;
#pragma unroll
            for (int d = 0; d < HDd; d++) oacc[d] += p * vs[j][d];
        }
        float* o = g_ATT + ((size_t)(win * Nn + tid)) * Cc + h * HDd;
#pragma unroll
        for (int d = 0; d < HDd; d++) o[d] = oacc[d];
    }
}

// --------------------------- launch ------------------------------------------
extern "C" void kernel_launch(void* const* d_in, const int* in_sizes, int n_in,
                              void* d_out, int out_size) {
    const float* x        = (const float*)d_in[0];
    const float* norm1_g  = (const float*)d_in[1];
    const float* norm1_b  = (const float*)d_in[2];
    const float* qkv_w    = (const float*)d_in[3];   // [576,192]
    const float* rel_bias = (const float*)d_in[4];   // [169,6]
    const float* proj_w   = (const float*)d_in[5];   // [192,192]
    const float* proj_b   = (const float*)d_in[6];
    const float* norm2_g  = (const float*)d_in[7];
    const float* norm2_b  = (const float*)d_in[8];
    const float* fc1_w    = (const float*)d_in[9];   // [768,192]
    const float* fc1_b    = (const float*)d_in[10];
    const float* fc2_w    = (const float*)d_in[11];  // [192,768]
    const float* fc2_b    = (const float*)d_in[12];
    float* out = (float*)d_out;

    float *XW, *QKV, *ATT, *XR, *XN2, *Hb;
    cudaGetSymbolAddress((void**)&XW,  g_XW);
    cudaGetSymbolAddress((void**)&QKV, g_QKV);
    cudaGetSymbolAddress((void**)&ATT, g_ATT);
    cudaGetSymbolAddress((void**)&XR,  g_XR);
    cudaGetSymbolAddress((void**)&XN2, g_XN2);
    cudaGetSymbolAddress((void**)&Hb,  g_H);

    cudaFuncSetAttribute(gemm_mma<0, 192>, cudaFuncAttributeMaxDynamicSharedMemorySize, SMEM_BYTES);
    cudaFuncSetAttribute(gemm_mma<1, 192>, cudaFuncAttributeMaxDynamicSharedMemorySize, SMEM_BYTES);
    cudaFuncSetAttribute(gemm_mma<2, 192>, cudaFuncAttributeMaxDynamicSharedMemorySize, SMEM_BYTES);
    cudaFuncSetAttribute(gemm_mma<3, 768>, cudaFuncAttributeMaxDynamicSharedMemorySize, SMEM_BYTES);

    // 1. LN1 + cyclic shift + window partition -> XW
    ln1_gather_kernel<<<TOT / 8, 256>>>(x, norm1_g, norm1_b);
    // 2. QKV: [100352,192] x [576,192]^T -> QKV
    gemm_mma<0, 192><<<dim3(TOT / BM, 576 / BN), 256, SMEM_BYTES>>>(XW, qkv_w, nullptr, nullptr, QKV, 3 * Cc);
    // 3. windowed attention
    attn_kernel<<<dim3(NHh, NWIN), 64>>>(rel_bias);
    // 4. proj + bias + reverse-window scatter + residual -> XR
    gemm_mma<1, 192><<<dim3(TOT / BM, Cc / BN), 256, SMEM_BYTES>>>(ATT, proj_w, proj_b, x, XR, Cc);
    // 5. LN2 -> XN2
    ln2_kernel<<<TOT / 8, 256>>>(norm2_g, norm2_b);
    // 6. FC1 + bias + exact GELU -> H
    gemm_mma<2, 192><<<dim3(TOT / BM, MLPH / BN), 256, SMEM_BYTES>>>(XN2, fc1_w, fc1_b, nullptr, Hb, MLPH);
    // 7. FC2 + bias + residual(XR) -> out
    gemm_mma<3, 768><<<dim3(TOT / BM, Cc / BN), 256, SMEM_BYTES>>>(Hb, fc2_w, fc2_b, XR, out, Cc);
}

// round 7
// speedup vs baseline: 3.5832x; 1.5980x over previous
#include <cuda_runtime.h>
#include <cuda_bf16.h>
#include <math.h>
#include <stdint.h>

// ---------------------------------------------------------------------------
// Swin block: B=32,H=W=56,C=192,NH=6,WS=7,SS=3,HD=32,N=49,MLP_H=768
// GEMMs via mma.sync m16n8k16 bf16 (portable sm_80+ path).
// Intermediates bf16; residual trunk fp32.
// ---------------------------------------------------------------------------

#define Bn     32
#define Hh     56
#define Ww     56
#define Cc     192
#define NHh    6
#define WSs    7
#define SSs    3
#define HDd    32
#define Nn     49
#define MLPH   768
#define Ltok   (Hh*Ww)
#define TOT    (Bn*Ltok)          // 100352
#define NWIN   2048
#define SCALEF 0.17677669529663687f

// GEMM tiling
#define BM   256
#define BN   64
#define BK   64                   // bf16 elems per K-chunk
#define PADE 72                   // smem row pitch in bf16 elems (144B, 16B-mult, conflict-free)
#define ABUFE (BM*PADE)           // bf16 elems per A buffer (18432)
#define BBUFE (BN*PADE)           // 4608
#define SMEM_BYTES ((2*ABUFE + 2*BBUFE) * 2)   // 92160

typedef __nv_bfloat16 bf16;
typedef __nv_bfloat162 bf162;

// ------------------------- scratch (device globals) ------------------------
__device__ bf16  g_XW [TOT * Cc];
__device__ bf16  g_QKV[TOT * 3 * Cc];
__device__ bf16  g_ATT[TOT * Cc];
__device__ float g_XR [TOT * Cc];
__device__ bf16  g_XN2[TOT * Cc];
__device__ bf16  g_H  [TOT * MLPH];
__device__ bf16  g_Wq [576 * Cc];
__device__ bf16  g_Wp [Cc * Cc];
__device__ bf16  g_W1 [MLPH * Cc];
__device__ bf16  g_W2 [Cc * MLPH];

// --------------------------- PTX helpers -----------------------------------
__device__ __forceinline__ uint32_t smem_u32(const void* p) {
    uint32_t a;
    asm("{ .reg .u64 t; cvta.to.shared.u64 t, %1; cvt.u32.u64 %0, t; }"
        : "=r"(a) : "l"(p));
    return a;
}

#define CP_ASYNC16(dst, src) \
    asm volatile("cp.async.cg.shared.global [%0], [%1], 16;" :: "r"(dst), "l"(src))
#define CP_COMMIT() asm volatile("cp.async.commit_group;")
#define CP_WAIT(n)  asm volatile("cp.async.wait_group %0;" :: "n"(n))

__device__ __forceinline__ void mma_bf16(float* c, const uint32_t* a, const uint32_t* b) {
    asm volatile(
        "mma.sync.aligned.m16n8k16.row.col.f32.bf16.bf16.f32 "
        "{%0,%1,%2,%3}, {%4,%5,%6,%7}, {%8,%9}, {%0,%1,%2,%3};"
        : "+f"(c[0]), "+f"(c[1]), "+f"(c[2]), "+f"(c[3])
        : "r"(a[0]), "r"(a[1]), "r"(a[2]), "r"(a[3]), "r"(b[0]), "r"(b[1]));
}

// --------------------- token <-> (shifted window) mapping ------------------
__device__ __forceinline__ int win_to_tok(int t) {
    int win = t / Nn, r = t - win * Nn;
    int b = win >> 6, w_ = win & 63;
    int wh = w_ >> 3, ww = w_ & 7;
    int ih = r / WSs, iw = r - ih * WSs;
    int rr = wh * WSs + ih + SSs; if (rr >= Hh) rr -= Hh;
    int cc = ww * WSs + iw + SSs; if (cc >= Ww) cc -= Ww;
    return b * Ltok + rr * Ww + cc;
}

// ----------------------- weight conversion to bf16 --------------------------
__global__ void wconv_kernel(const float* __restrict__ qw, const float* __restrict__ pw,
                             const float* __restrict__ w1, const float* __restrict__ w2) {
    int i = blockIdx.x * blockDim.x + threadIdx.x;
    if (i < 576 * Cc)  g_Wq[i] = __float2bfloat16(qw[i]);
    if (i < Cc * Cc)   g_Wp[i] = __float2bfloat16(pw[i]);
    if (i < MLPH * Cc) g_W1[i] = __float2bfloat16(w1[i]);
    if (i < Cc * MLPH) g_W2[i] = __float2bfloat16(w2[i]);
}

// --------------------------- LN kernels -------------------------------------
__global__ void ln1_gather_kernel(const float* __restrict__ x,
                                  const float* __restrict__ g,
                                  const float* __restrict__ bt) {
    int warp = (blockIdx.x * blockDim.x + threadIdx.x) >> 5;
    int lane = threadIdx.x & 31;
    if (warp >= TOT) return;
    const float* src = x + (size_t)win_to_tok(warp) * Cc;
    float v[6], s = 0.f, ss = 0.f;
#pragma unroll
    for (int k = 0; k < 6; k++) { v[k] = src[lane + k * 32]; s += v[k]; ss += v[k] * v[k]; }
#pragma unroll
    for (int o = 16; o; o >>= 1) {
        s  += __shfl_xor_sync(0xffffffffu, s, o);
        ss += __shfl_xor_sync(0xffffffffu, ss, o);
    }
    float mu = s * (1.f / Cc);
    float rstd = rsqrtf(ss * (1.f / Cc) - mu * mu + 1e-5f);
    bf16* dst = g_XW + (size_t)warp * Cc;
#pragma unroll
    for (int k = 0; k < 6; k++) {
        int c = lane + k * 32;
        dst[c] = __float2bfloat16((v[k] - mu) * rstd * g[c] + bt[c]);
    }
}

__global__ void ln2_kernel(const float* __restrict__ g,
                           const float* __restrict__ bt) {
    int warp = (blockIdx.x * blockDim.x + threadIdx.x) >> 5;
    int lane = threadIdx.x & 31;
    if (warp >= TOT) return;
    const float* src = g_XR + (size_t)warp * Cc;
    float v[6], s = 0.f, ss = 0.f;
#pragma unroll
    for (int k = 0; k < 6; k++) { v[k] = src[lane + k * 32]; s += v[k]; ss += v[k] * v[k]; }
#pragma unroll
    for (int o = 16; o; o >>= 1) {
        s  += __shfl_xor_sync(0xffffffffu, s, o);
        ss += __shfl_xor_sync(0xffffffffu, ss, o);
    }
    float mu = s * (1.f / Cc);
    float rstd = rsqrtf(ss * (1.f / Cc) - mu * mu + 1e-5f);
    bf16* dst = g_XN2 + (size_t)warp * Cc;
#pragma unroll
    for (int k = 0; k < 6; k++) {
        int c = lane + k * 32;
        dst[c] = __float2bfloat16((v[k] - mu) * rstd * g[c] + bt[c]);
    }
}

// --------------------------- bf16 mma GEMM ----------------------------------
// C[M,Nd] = A[M,KK] * W[Nd,KK]^T, bf16 in, fp32 accum.
// CTA 256x64, K-chunk 64, cp.async double-buffered.
// 8 warps: 4(M) x 2(N), warp tile 64x32 (4x4 m16n8k16 frags).
// EPI: 0 plain->bf16, 1 proj(bias+scatter+residual fp32->XR),
//      2 bias+gelu->bf16, 3 bias+residual->fp32 out.
template <int EPI, int KK>
__global__ __launch_bounds__(256)
void gemm_mma(const bf16* __restrict__ A, const bf16* __restrict__ W,
              const float* __restrict__ bias, const float* __restrict__ res,
              void* __restrict__ outp, int Nd) {
    constexpr int NC = KK / BK;
    extern __shared__ __align__(16) bf16 smem[];
    bf16* As[2] = {smem, smem + ABUFE};
    bf16* Bs[2] = {smem + 2 * ABUFE, smem + 2 * ABUFE + BBUFE};
    const uint32_t as_u[2] = {smem_u32(As[0]), smem_u32(As[1])};
    const uint32_t bs_u[2] = {smem_u32(Bs[0]), smem_u32(Bs[1])};

    const int tid = threadIdx.x;
    const int wid = tid >> 5;
    const int lane = tid & 31;
    const int gr = lane >> 2, gc = lane & 3;
    const int wm = wid >> 1;
    const int wn = wid & 1;
    const int mbase = blockIdx.x * BM;
    const int nbase = blockIdx.y * BN;

    const bf16* Ab = A + (size_t)mbase * KK;
    const bf16* Wb = W + (size_t)nbase * KK;

    float acc[4][4][4];
#pragma unroll
    for (int i = 0; i < 4; i++)
#pragma unroll
        for (int j = 0; j < 4; j++)
#pragma unroll
            for (int k = 0; k < 4; k++) acc[i][j][k] = 0.f;

    // prologue: chunk 0  (rows are 128B of data in 144B-pitched smem)
#pragma unroll
    for (int i = tid; i < BM * 8; i += 256) {
        int row = i >> 3, seg = i & 7;
        CP_ASYNC16(as_u[0] + (uint32_t)(row * 144 + seg * 16),
                   Ab + (size_t)row * KK + seg * 8);
    }
#pragma unroll
    for (int i = tid; i < BN * 8; i += 256) {
        int row = i >> 3, seg = i & 7;
        CP_ASYNC16(bs_u[0] + (uint32_t)(row * 144 + seg * 16),
                   Wb + (size_t)row * KK + seg * 8);
    }
    CP_COMMIT();

    for (int c = 0; c < NC; ++c) {
        if (c + 1 < NC) {
            const int nb = (c + 1) & 1;
            const int ko = (c + 1) * BK;
#pragma unroll
            for (int i = tid; i < BM * 8; i += 256) {
                int row = i >> 3, seg = i & 7;
                CP_ASYNC16(as_u[nb] + (uint32_t)(row * 144 + seg * 16),
                           Ab + (size_t)row * KK + ko + seg * 8);
            }
#pragma unroll
            for (int i = tid; i < BN * 8; i += 256) {
                int row = i >> 3, seg = i & 7;
                CP_ASYNC16(bs_u[nb] + (uint32_t)(row * 144 + seg * 16),
                           Wb + (size_t)row * KK + ko + seg * 8);
            }
            CP_COMMIT();
            CP_WAIT(1);
        } else {
            CP_WAIT(0);
        }
        __syncthreads();

        // uint32 views, row pitch 36 u32 (= 72 bf16)
        const uint32_t* A32 = (const uint32_t*)As[c & 1];
        const uint32_t* B32 = (const uint32_t*)Bs[c & 1];
#pragma unroll
        for (int ks = 0; ks < 4; ++ks) {
            const int kq = ks * 8;  // k offset in u32 units (16 bf16 per step)
            uint32_t af[4][4], bf[4][2];
#pragma unroll
            for (int mi = 0; mi < 4; ++mi) {
                int r0 = wm * 64 + mi * 16 + gr;
                af[mi][0] = A32[r0 * 36 + kq + gc];
                af[mi][1] = A32[(r0 + 8) * 36 + kq + gc];
                af[mi][2] = A32[r0 * 36 + kq + gc + 4];
                af[mi][3] = A32[(r0 + 8) * 36 + kq + gc + 4];
            }
#pragma unroll
            for (int ni = 0; ni < 4; ++ni) {
                int nr = wn * 32 + ni * 8 + gr;
                bf[ni][0] = B32[nr * 36 + kq + gc];
                bf[ni][1] = B32[nr * 36 + kq + gc + 4];
            }
#pragma unroll
            for (int mi = 0; mi < 4; ++mi)
#pragma unroll
                for (int ni = 0; ni < 4; ++ni)
                    mma_bf16(acc[mi][ni], af[mi], bf[ni]);
        }
        __syncthreads();
    }

    // ----------------------- fused epilogue ---------------------------------
#pragma unroll
    for (int mi = 0; mi < 4; ++mi) {
#pragma unroll
        for (int half = 0; half < 2; ++half) {
            int row = mbase + wm * 64 + mi * 16 + gr + half * 8;
            int orow = row;
            if (EPI == 1) orow = win_to_tok(row);
#pragma unroll
            for (int ni = 0; ni < 4; ++ni) {
                int col = nbase + wn * 32 + ni * 8 + gc * 2;
                float v0 = acc[mi][ni][half * 2 + 0];
                float v1 = acc[mi][ni][half * 2 + 1];
                if (EPI == 0) {
                    bf162 ob;
                    ob.x = __float2bfloat16(v0);
                    ob.y = __float2bfloat16(v1);
                    *(bf162*)((bf16*)outp + (size_t)orow * Nd + col) = ob;
                } else if (EPI == 1) {
                    const float* rp = res + (size_t)orow * Nd + col;
                    float2 o = make_float2(v0 + bias[col] + rp[0],
                                           v1 + bias[col + 1] + rp[1]);
                    *(float2*)((float*)outp + (size_t)orow * Nd + col) = o;
                } else if (EPI == 2) {
                    float a0 = v0 + bias[col], a1 = v1 + bias[col + 1];
                    const float kc = 0.70710678118654752f;
                    bf162 ob;
                    ob.x = __float2bfloat16(0.5f * a0 * (1.f + erff(a0 * kc)));
                    ob.y = __float2bfloat16(0.5f * a1 * (1.f + erff(a1 * kc)));
                    *(bf162*)((bf16*)outp + (size_t)orow * Nd + col) = ob;
                } else { // EPI == 3
                    const float* rp = res + (size_t)row * Nd + col;
                    float2 o = make_float2(v0 + bias[col] + rp[0],
                                           v1 + bias[col + 1] + rp[1]);
                    *(float2*)((float*)outp + (size_t)orow * Nd + col) = o;
                }
            }
        }
    }
}

// --------------------------- attention --------------------------------------
__device__ __forceinline__ int region_label(int R, int Cg) {
    int lr = (R  < Hh - WSs) ? 0 : ((R  < Hh - SSs) ? 1 : 2);
    int lc = (Cg < Ww - WSs) ? 0 : ((Cg < Ww - SSs) ? 1 : 2);
    return lr * 3 + lc;
}

__global__ __launch_bounds__(64)
void attn_kernel(const float* __restrict__ bias_table) {
    int h   = blockIdx.x;
    int win = blockIdx.y;
    __shared__ float ks[Nn][HDd];
    __shared__ float vs[Nn][HDd];
    int tid = threadIdx.x;
    const bf16* base = g_QKV + (size_t)win * Nn * (3 * Cc);

    for (int idx = tid; idx < Nn * 16; idx += 64) {
        int j = idx >> 4, d2 = (idx & 15) * 2;
        bf162 k2 = *(const bf162*)(base + j * (3 * Cc) + Cc     + h * HDd + d2);
        bf162 v2 = *(const bf162*)(base + j * (3 * Cc) + 2 * Cc + h * HDd + d2);
        ks[j][d2] = __bfloat162float(k2.x); ks[j][d2 + 1] = __bfloat162float(k2.y);
        vs[j][d2] = __bfloat162float(v2.x); vs[j][d2 + 1] = __bfloat162float(v2.y);
    }
    __syncthreads();

    if (tid < Nn) {
        int ih = tid / WSs, iw = tid - ih * WSs;
        int wh = (win & 63) >> 3, ww = win & 7;
        int li = region_label(wh * WSs + ih, ww * WSs + iw);

        float q[HDd];
        const bf16* qp = base + tid * (3 * Cc) + h * HDd;
#pragma unroll
        for (int d2 = 0; d2 < HDd; d2 += 2) {
            bf162 q2 = *(const bf162*)(qp + d2);
            q[d2] = __bfloat162float(q2.x) * SCALEF;
            q[d2 + 1] = __bfloat162float(q2.y) * SCALEF;
        }

        float sarr[Nn];
        float mx = -1e30f;
        for (int j = 0; j < Nn; j++) {
            int jh = j / WSs, jw = j - jh * WSs;
            int lj = region_label(wh * WSs + jh, ww * WSs + jw);
            int ridx = (ih - jh + WSs - 1) * (2 * WSs - 1) + (iw - jw + WSs - 1);
            float s = bias_table[ridx * NHh + h] + ((li != lj) ? -100.f : 0.f);
#pragma unroll
            for (int d = 0; d < HDd; d++) s += q[d] * ks[j][d];
            sarr[j] = s;
            mx = fmaxf(mx, s);
        }
        float sum = 0.f;
        for (int j = 0; j < Nn; j++) { sarr[j] = expf(sarr[j] - mx); sum += sarr[j]; }
        float inv = 1.f / sum;

        float oacc[HDd];
#pragma unroll
        for (int d = 0; d < HDd; d++) oacc[d] = 0.f;
        for (int j = 0; j < Nn; j++) {
            float p = sarr[j] * inv;
#pragma unroll
            for (int d = 0; d < HDd; d++) oacc[d] += p * vs[j][d];
        }
        bf16* o = g_ATT + ((size_t)(win * Nn + tid)) * Cc + h * HDd;
#pragma unroll
        for (int d2 = 0; d2 < HDd; d2 += 2) {
            bf162 ob;
            ob.x = __float2bfloat16(oacc[d2]);
            ob.y = __float2bfloat16(oacc[d2 + 1]);
            *(bf162*)(o + d2) = ob;
        }
    }
}

// --------------------------- launch ------------------------------------------
extern "C" void kernel_launch(void* const* d_in, const int* in_sizes, int n_in,
                              void* d_out, int out_size) {
    const float* x        = (const float*)d_in[0];
    const float* norm1_g  = (const float*)d_in[1];
    const float* norm1_b  = (const float*)d_in[2];
    const float* qkv_w    = (const float*)d_in[3];
    const float* rel_bias = (const float*)d_in[4];
    const float* proj_w   = (const float*)d_in[5];
    const float* proj_b   = (const float*)d_in[6];
    const float* norm2_g  = (const float*)d_in[7];
    const float* norm2_b  = (const float*)d_in[8];
    const float* fc1_w    = (const float*)d_in[9];
    const float* fc1_b    = (const float*)d_in[10];
    const float* fc2_w    = (const float*)d_in[11];
    const float* fc2_b    = (const float*)d_in[12];
    float* out = (float*)d_out;

    bf16 *XW, *QKV, *ATT, *XN2, *Hb, *Wq, *Wp, *W1, *W2;
    float *XR;
    cudaGetSymbolAddress((void**)&XW,  g_XW);
    cudaGetSymbolAddress((void**)&QKV, g_QKV);
    cudaGetSymbolAddress((void**)&ATT, g_ATT);
    cudaGetSymbolAddress((void**)&XR,  g_XR);
    cudaGetSymbolAddress((void**)&XN2, g_XN2);
    cudaGetSymbolAddress((void**)&Hb,  g_H);
    cudaGetSymbolAddress((void**)&Wq,  g_Wq);
    cudaGetSymbolAddress((void**)&Wp,  g_Wp);
    cudaGetSymbolAddress((void**)&W1,  g_W1);
    cudaGetSymbolAddress((void**)&W2,  g_W2);

    cudaFuncSetAttribute(gemm_mma<0, 192>, cudaFuncAttributeMaxDynamicSharedMemorySize, SMEM_BYTES);
    cudaFuncSetAttribute(gemm_mma<1, 192>, cudaFuncAttributeMaxDynamicSharedMemorySize, SMEM_BYTES);
    cudaFuncSetAttribute(gemm_mma<2, 192>, cudaFuncAttributeMaxDynamicSharedMemorySize, SMEM_BYTES);
    cudaFuncSetAttribute(gemm_mma<3, 768>, cudaFuncAttributeMaxDynamicSharedMemorySize, SMEM_BYTES);

    // 0. weights -> bf16
    wconv_kernel<<<(MLPH * Cc + 255) / 256, 256>>>(qkv_w, proj_w, fc1_w, fc2_w);
    // 1. LN1 + cyclic shift + window partition -> XW (bf16)
    ln1_gather_kernel<<<TOT / 8, 256>>>(x, norm1_g, norm1_b);
    // 2. QKV gemm -> QKV (bf16)
    gemm_mma<0, 192><<<dim3(TOT / BM, 576 / BN), 256, SMEM_BYTES>>>(XW, Wq, nullptr, nullptr, QKV, 3 * Cc);
    // 3. windowed attention -> ATT (bf16)
    attn_kernel<<<dim3(NHh, NWIN), 64>>>(rel_bias);
    // 4. proj + bias + reverse scatter + residual -> XR (fp32)
    gemm_mma<1, 192><<<dim3(TOT / BM, Cc / BN), 256, SMEM_BYTES>>>(ATT, Wp, proj_b, x, XR, Cc);
    // 5. LN2 -> XN2 (bf16)
    ln2_kernel<<<TOT / 8, 256>>>(norm2_g, norm2_b);
    // 6. FC1 + bias + exact GELU -> H (bf16)
    gemm_mma<2, 192><<<dim3(TOT / BM, MLPH / BN), 256, SMEM_BYTES>>>(XN2, W1, fc1_b, nullptr, Hb, MLPH);
    // 7. FC2 + bias + residual(XR) -> out (fp32)
    gemm_mma<3, 768><<<dim3(TOT / BM, Cc / BN), 256, SMEM_BYTES>>>(Hb, W2, fc2_b, XR, out, Cc);
}

// round 8
// speedup vs baseline: 4.1672x; 1.1630x over previous
#include <cuda_runtime.h>
#include <cuda_bf16.h>
#include <math.h>
#include <stdint.h>

// ---------------------------------------------------------------------------
// Swin block: B=32,H=W=56,C=192,NH=6,WS=7,SS=3,HD=32,N=49,MLP_H=768
// GEMMs + attention via mma.sync m16n8k16 bf16 (portable sm_80+ path).
// ---------------------------------------------------------------------------

#define Bn     32
#define Hh     56
#define Ww     56
#define Cc     192
#define NHh    6
#define WSs    7
#define SSs    3
#define HDd    32
#define Nn     49
#define MLPH   768
#define Ltok   (Hh*Ww)
#define TOT    (Bn*Ltok)          // 100352
#define NWIN   2048
#define SCALEF 0.17677669529663687f

// GEMM tiling
#define BM   256
#define BN   64
#define BK   64
#define PADE 72
#define ABUFE (BM*PADE)
#define BBUFE (BN*PADE)
#define SMEM_BYTES ((2*ABUFE + 2*BBUFE) * 2)   // 92160

typedef __nv_bfloat16 bf16;
typedef __nv_bfloat162 bf162;

// ------------------------- scratch (device globals) ------------------------
__device__ bf16  g_XW [TOT * Cc];
__device__ bf16  g_QKV[TOT * 3 * Cc];
__device__ bf16  g_ATT[TOT * Cc];
__device__ float g_XR [TOT * Cc];
__device__ bf16  g_XN2[TOT * Cc];
__device__ bf16  g_H  [TOT * MLPH];
__device__ bf16  g_Wq [576 * Cc];
__device__ bf16  g_Wp [Cc * Cc];
__device__ bf16  g_W1 [MLPH * Cc];
__device__ bf16  g_W2 [Cc * MLPH];
__device__ float g_BM [4 * NHh * 64 * 64];   // bias+mask per window-type/head

// --------------------------- PTX helpers -----------------------------------
__device__ __forceinline__ uint32_t smem_u32(const void* p) {
    uint32_t a;
    asm("{ .reg .u64 t; cvta.to.shared.u64 t, %1; cvt.u32.u64 %0, t; }"
        : "=r"(a) : "l"(p));
    return a;
}

#define CP_ASYNC16(dst, src) \
    asm volatile("cp.async.cg.shared.global [%0], [%1], 16;" :: "r"(dst), "l"(src))
#define CP_COMMIT() asm volatile("cp.async.commit_group;")
#define CP_WAIT(n)  asm volatile("cp.async.wait_group %0;" :: "n"(n))

__device__ __forceinline__ void mma_bf16(float* c, const uint32_t* a, const uint32_t* b) {
    asm volatile(
        "mma.sync.aligned.m16n8k16.row.col.f32.bf16.bf16.f32 "
        "{%0,%1,%2,%3}, {%4,%5,%6,%7}, {%8,%9}, {%0,%1,%2,%3};"
        : "+f"(c[0]), "+f"(c[1]), "+f"(c[2]), "+f"(c[3])
        : "r"(a[0]), "r"(a[1]), "r"(a[2]), "r"(a[3]), "r"(b[0]), "r"(b[1]));
}

// pack {lo, hi} floats into bf16x2 (lo -> low 16 bits)
__device__ __forceinline__ uint32_t packbf(float lo, float hi) {
    uint32_t r;
    asm("cvt.rn.bf16x2.f32 %0, %1, %2;" : "=r"(r) : "f"(hi), "f"(lo));
    return r;
}

// --------------------- token <-> (shifted window) mapping ------------------
__device__ __forceinline__ int win_to_tok(int t) {
    int win = t / Nn, r = t - win * Nn;
    int b = win >> 6, w_ = win & 63;
    int wh = w_ >> 3, ww = w_ & 7;
    int ih = r / WSs, iw = r - ih * WSs;
    int rr = wh * WSs + ih + SSs; if (rr >= Hh) rr -= Hh;
    int cc = ww * WSs + iw + SSs; if (cc >= Ww) cc -= Ww;
    return b * Ltok + rr * Ww + cc;
}

// ----------------------- weight conversion to bf16 --------------------------
__global__ void wconv_kernel(const float* __restrict__ qw, const float* __restrict__ pw,
                             const float* __restrict__ w1, const float* __restrict__ w2) {
    int i = blockIdx.x * blockDim.x + threadIdx.x;
    if (i < 576 * Cc)  g_Wq[i] = __float2bfloat16(qw[i]);
    if (i < Cc * Cc)   g_Wp[i] = __float2bfloat16(pw[i]);
    if (i < MLPH * Cc) g_W1[i] = __float2bfloat16(w1[i]);
    if (i < Cc * MLPH) g_W2[i] = __float2bfloat16(w2[i]);
}

// -------------------- bias + shift-mask table init -------------------------
// g_BM[wt][h][i][j], wt = 2*(wh==7) + (ww==7); invalid i/j -> -1e30.
__global__ void bm_init_kernel(const float* __restrict__ tbl) {
    int idx = blockIdx.x * blockDim.x + threadIdx.x;
    if (idx >= 4 * NHh * 64 * 64) return;
    int j = idx & 63, i = (idx >> 6) & 63;
    int hh = (idx >> 12) % NHh, wt = (idx >> 12) / NHh;
    float v;
    if (i < Nn && j < Nn) {
        int ih = i / 7, iw = i % 7, jh = j / 7, jw = j % 7;
        int ridx = (ih - jh + 6) * 13 + (iw - jw + 6);
        v = tbl[ridx * NHh + hh];
        int th = wt >> 1, tw = wt & 1;
        int li = (th ? (ih < 4 ? 1 : 2) : 0) * 3 + (tw ? (iw < 4 ? 1 : 2) : 0);
        int lj = (th ? (jh < 4 ? 1 : 2) : 0) * 3 + (tw ? (jw < 4 ? 1 : 2) : 0);
        if (li != lj) v -= 100.f;
    } else {
        v = -1e30f;
    }
    g_BM[idx] = v;
}

// --------------------------- LN kernels -------------------------------------
__global__ void ln1_gather_kernel(const float* __restrict__ x,
                                  const float* __restrict__ g,
                                  const float* __restrict__ bt) {
    int warp = (blockIdx.x * blockDim.x + threadIdx.x) >> 5;
    int lane = threadIdx.x & 31;
    if (warp >= TOT) return;
    const float* src = x + (size_t)win_to_tok(warp) * Cc;
    float v[6], s = 0.f, ss = 0.f;
#pragma unroll
    for (int k = 0; k < 6; k++) { v[k] = src[lane + k * 32]; s += v[k]; ss += v[k] * v[k]; }
#pragma unroll
    for (int o = 16; o; o >>= 1) {
        s  += __shfl_xor_sync(0xffffffffu, s, o);
        ss += __shfl_xor_sync(0xffffffffu, ss, o);
    }
    float mu = s * (1.f / Cc);
    float rstd = rsqrtf(ss * (1.f / Cc) - mu * mu + 1e-5f);
    bf16* dst = g_XW + (size_t)warp * Cc;
#pragma unroll
    for (int k = 0; k < 6; k++) {
        int c = lane + k * 32;
        dst[c] = __float2bfloat16((v[k] - mu) * rstd * g[c] + bt[c]);
    }
}

__global__ void ln2_kernel(const float* __restrict__ g,
                           const float* __restrict__ bt) {
    int warp = (blockIdx.x * blockDim.x + threadIdx.x) >> 5;
    int lane = threadIdx.x & 31;
    if (warp >= TOT) return;
    const float* src = g_XR + (size_t)warp * Cc;
    float v[6], s = 0.f, ss = 0.f;
#pragma unroll
    for (int k = 0; k < 6; k++) { v[k] = src[lane + k * 32]; s += v[k]; ss += v[k] * v[k]; }
#pragma unroll
    for (int o = 16; o; o >>= 1) {
        s  += __shfl_xor_sync(0xffffffffu, s, o);
        ss += __shfl_xor_sync(0xffffffffu, ss, o);
    }
    float mu = s * (1.f / Cc);
    float rstd = rsqrtf(ss * (1.f / Cc) - mu * mu + 1e-5f);
    bf16* dst = g_XN2 + (size_t)warp * Cc;
#pragma unroll
    for (int k = 0; k < 6; k++) {
        int c = lane + k * 32;
        dst[c] = __float2bfloat16((v[k] - mu) * rstd * g[c] + bt[c]);
    }
}

// --------------------------- bf16 mma GEMM ----------------------------------
template <int EPI, int KK>
__global__ __launch_bounds__(256)
void gemm_mma(const bf16* __restrict__ A, const bf16* __restrict__ W,
              const float* __restrict__ bias, const float* __restrict__ res,
              void* __restrict__ outp, int Nd) {
    constexpr int NC = KK / BK;
    extern __shared__ __align__(16) bf16 smem[];
    bf16* As[2] = {smem, smem + ABUFE};
    bf16* Bs[2] = {smem + 2 * ABUFE, smem + 2 * ABUFE + BBUFE};
    const uint32_t as_u[2] = {smem_u32(As[0]), smem_u32(As[1])};
    const uint32_t bs_u[2] = {smem_u32(Bs[0]), smem_u32(Bs[1])};

    const int tid = threadIdx.x;
    const int wid = tid >> 5;
    const int lane = tid & 31;
    const int gr = lane >> 2, gc = lane & 3;
    const int wm = wid >> 1;
    const int wn = wid & 1;
    const int mbase = blockIdx.x * BM;
    const int nbase = blockIdx.y * BN;

    const bf16* Ab = A + (size_t)mbase * KK;
    const bf16* Wb = W + (size_t)nbase * KK;

    float acc[4][4][4];
#pragma unroll
    for (int i = 0; i < 4; i++)
#pragma unroll
        for (int j = 0; j < 4; j++)
#pragma unroll
            for (int k = 0; k < 4; k++) acc[i][j][k] = 0.f;

#pragma unroll
    for (int i = tid; i < BM * 8; i += 256) {
        int row = i >> 3, seg = i & 7;
        CP_ASYNC16(as_u[0] + (uint32_t)(row * 144 + seg * 16),
                   Ab + (size_t)row * KK + seg * 8);
    }
#pragma unroll
    for (int i = tid; i < BN * 8; i += 256) {
        int row = i >> 3, seg = i & 7;
        CP_ASYNC16(bs_u[0] + (uint32_t)(row * 144 + seg * 16),
                   Wb + (size_t)row * KK + seg * 8);
    }
    CP_COMMIT();

    for (int c = 0; c < NC; ++c) {
        if (c + 1 < NC) {
            const int nb = (c + 1) & 1;
            const int ko = (c + 1) * BK;
#pragma unroll
            for (int i = tid; i < BM * 8; i += 256) {
                int row = i >> 3, seg = i & 7;
                CP_ASYNC16(as_u[nb] + (uint32_t)(row * 144 + seg * 16),
                           Ab + (size_t)row * KK + ko + seg * 8);
            }
#pragma unroll
            for (int i = tid; i < BN * 8; i += 256) {
                int row = i >> 3, seg = i & 7;
                CP_ASYNC16(bs_u[nb] + (uint32_t)(row * 144 + seg * 16),
                           Wb + (size_t)row * KK + ko + seg * 8);
            }
            CP_COMMIT();
            CP_WAIT(1);
        } else {
            CP_WAIT(0);
        }
        __syncthreads();

        const uint32_t* A32 = (const uint32_t*)As[c & 1];
        const uint32_t* B32 = (const uint32_t*)Bs[c & 1];
#pragma unroll
        for (int ks = 0; ks < 4; ++ks) {
            const int kq = ks * 8;
            uint32_t af[4][4], bfr[4][2];
#pragma unroll
            for (int mi = 0; mi < 4; ++mi) {
                int r0 = wm * 64 + mi * 16 + gr;
                af[mi][0] = A32[r0 * 36 + kq + gc];
                af[mi][1] = A32[(r0 + 8) * 36 + kq + gc];
                af[mi][2] = A32[r0 * 36 + kq + gc + 4];
                af[mi][3] = A32[(r0 + 8) * 36 + kq + gc + 4];
            }
#pragma unroll
            for (int ni = 0; ni < 4; ++ni) {
                int nr = wn * 32 + ni * 8 + gr;
                bfr[ni][0] = B32[nr * 36 + kq + gc];
                bfr[ni][1] = B32[nr * 36 + kq + gc + 4];
            }
#pragma unroll
            for (int mi = 0; mi < 4; ++mi)
#pragma unroll
                for (int ni = 0; ni < 4; ++ni)
                    mma_bf16(acc[mi][ni], af[mi], bfr[ni]);
        }
        __syncthreads();
    }

#pragma unroll
    for (int mi = 0; mi < 4; ++mi) {
#pragma unroll
        for (int half = 0; half < 2; ++half) {
            int row = mbase + wm * 64 + mi * 16 + gr + half * 8;
            int orow = row;
            if (EPI == 1) orow = win_to_tok(row);
#pragma unroll
            for (int ni = 0; ni < 4; ++ni) {
                int col = nbase + wn * 32 + ni * 8 + gc * 2;
                float v0 = acc[mi][ni][half * 2 + 0];
                float v1 = acc[mi][ni][half * 2 + 1];
                if (EPI == 0) {
                    *(uint32_t*)((bf16*)outp + (size_t)orow * Nd + col) = packbf(v0, v1);
                } else if (EPI == 1) {
                    const float* rp = res + (size_t)orow * Nd + col;
                    float2 o = make_float2(v0 + bias[col] + rp[0],
                                           v1 + bias[col + 1] + rp[1]);
                    *(float2*)((float*)outp + (size_t)orow * Nd + col) = o;
                } else if (EPI == 2) {
                    float a0 = v0 + bias[col], a1 = v1 + bias[col + 1];
                    const float kc = 0.70710678118654752f;
                    *(uint32_t*)((bf16*)outp + (size_t)orow * Nd + col) =
                        packbf(0.5f * a0 * (1.f + erff(a0 * kc)),
                               0.5f * a1 * (1.f + erff(a1 * kc)));
                } else {
                    const float* rp = res + (size_t)row * Nd + col;
                    float2 o = make_float2(v0 + bias[col] + rp[0],
                                           v1 + bias[col + 1] + rp[1]);
                    *(float2*)((float*)outp + (size_t)orow * Nd + col) = o;
                }
            }
        }
    }
}

// --------------------------- mma attention ----------------------------------
// One CTA per window, 384 threads = 12 warps; 2 warps per head (32 queries each).
// smem per head (u32 words): Qs 64x20, Ks 64x20, Vt 32x36  => 3712 words.
#define ATTN_SMEM_BYTES (6 * 3712 * 4)   // 89088

__global__ __launch_bounds__(384, 1)
void attn_mma_kernel() {
    extern __shared__ uint32_t sm32[];
    const int tid = threadIdx.x;
    const int win = blockIdx.x;
    const int h = tid >> 6;          // head 0..5
    const int t2 = tid & 63;

    uint32_t* Qs = sm32 + h * 3712;
    uint32_t* Ks = Qs + 1280;        // 64*20
    uint32_t* Vt = Ks + 1280;

    // zero this head's region (covers padding rows/cols)
    for (int i = t2; i < 3712; i += 64) Qs[i] = 0;
    __syncthreads();

    const uint32_t* qkv = (const uint32_t*)g_QKV + (size_t)win * Nn * 288;
    bf16* vtb = (bf16*)Vt;
    for (int i = t2; i < Nn * 16; i += 64) {
        int row = i >> 4, wd = i & 15;
        const uint32_t* tp = qkv + row * 288 + h * 16 + wd;
        Qs[row * 20 + wd] = tp[0];
        Ks[row * 20 + wd] = tp[96];
        uint32_t vv = tp[192];
        bf162 v2 = *(bf162*)&vv;
        vtb[(2 * wd) * 72 + row]     = v2.x;
        vtb[(2 * wd + 1) * 72 + row] = v2.y;
    }
    __syncthreads();

    const int w = tid >> 5;
    const int lane = tid & 31;
    const int gr = lane >> 2, gc = lane & 3;
    const int qb = (w & 1) * 32;
    const int wh = (win & 63) >> 3, ww = win & 7;
    const int wt = ((wh == 7) ? 2 : 0) + ((ww == 7) ? 1 : 0);
    const float* bmp = g_BM + ((size_t)(wt * NHh + h) << 12);

    // ---- S = Q K^T (64 keys x 32 queries per warp) ----
    float sacc[2][8][4];
#pragma unroll
    for (int a = 0; a < 2; a++)
#pragma unroll
        for (int b = 0; b < 8; b++)
#pragma unroll
            for (int cse = 0; cse < 4; cse++) sacc[a][b][cse] = 0.f;

#pragma unroll
    for (int kst = 0; kst < 2; ++kst) {
        uint32_t af[2][4], bfr[8][2];
#pragma unroll
        for (int mt = 0; mt < 2; ++mt) {
            int r = qb + mt * 16 + gr;
            af[mt][0] = Qs[r * 20 + kst * 8 + gc];
            af[mt][1] = Qs[(r + 8) * 20 + kst * 8 + gc];
            af[mt][2] = Qs[r * 20 + kst * 8 + gc + 4];
            af[mt][3] = Qs[(r + 8) * 20 + kst * 8 + gc + 4];
        }
#pragma unroll
        for (int nt = 0; nt < 8; ++nt) {
            int j = nt * 8 + gr;
            bfr[nt][0] = Ks[j * 20 + kst * 8 + gc];
            bfr[nt][1] = Ks[j * 20 + kst * 8 + gc + 4];
        }
#pragma unroll
        for (int mt = 0; mt < 2; ++mt)
#pragma unroll
            for (int nt = 0; nt < 8; ++nt)
                mma_bf16(sacc[mt][nt], af[mt], bfr[nt]);
    }

    // ---- softmax (scale + bias + mask from g_BM; quad-shuffle reductions) ----
    float invr[2][2];
#pragma unroll
    for (int mt = 0; mt < 2; ++mt) {
#pragma unroll
        for (int hf = 0; hf < 2; ++hf) {
            int row = qb + mt * 16 + gr + hf * 8;
            const float* bmr = bmp + row * 64 + 2 * gc;
            float v[8][2], mx = -3e38f;
#pragma unroll
            for (int nt = 0; nt < 8; ++nt) {
                float2 bm2 = *(const float2*)(bmr + nt * 8);
                v[nt][0] = sacc[mt][nt][hf * 2 + 0] * SCALEF + bm2.x;
                v[nt][1] = sacc[mt][nt][hf * 2 + 1] * SCALEF + bm2.y;
                mx = fmaxf(mx, fmaxf(v[nt][0], v[nt][1]));
            }
            mx = fmaxf(mx, __shfl_xor_sync(0xffffffffu, mx, 1));
            mx = fmaxf(mx, __shfl_xor_sync(0xffffffffu, mx, 2));
            float sum = 0.f;
#pragma unroll
            for (int nt = 0; nt < 8; ++nt) {
                float e0 = __expf(v[nt][0] - mx);
                float e1 = __expf(v[nt][1] - mx);
                sacc[mt][nt][hf * 2 + 0] = e0;
                sacc[mt][nt][hf * 2 + 1] = e1;
                sum += e0 + e1;
            }
            sum += __shfl_xor_sync(0xffffffffu, sum, 1);
            sum += __shfl_xor_sync(0xffffffffu, sum, 2);
            invr[mt][hf] = 1.f / sum;
        }
    }

    // ---- O = P V  (P packed from sacc; V from Vt) ----
    float o[2][4][4];
#pragma unroll
    for (int a = 0; a < 2; a++)
#pragma unroll
        for (int b = 0; b < 4; b++)
#pragma unroll
            for (int cse = 0; cse < 4; cse++) o[a][b][cse] = 0.f;

#pragma unroll
    for (int k2 = 0; k2 < 4; ++k2) {
        uint32_t pf[2][4];
#pragma unroll
        for (int mt = 0; mt < 2; ++mt) {
            pf[mt][0] = packbf(sacc[mt][2 * k2][0],     sacc[mt][2 * k2][1]);
            pf[mt][1] = packbf(sacc[mt][2 * k2][2],     sacc[mt][2 * k2][3]);
            pf[mt][2] = packbf(sacc[mt][2 * k2 + 1][0], sacc[mt][2 * k2 + 1][1]);
            pf[mt][3] = packbf(sacc[mt][2 * k2 + 1][2], sacc[mt][2 * k2 + 1][3]);
        }
#pragma unroll
        for (int ntd = 0; ntd < 4; ++ntd) {
            uint32_t bv[2];
            int d = ntd * 8 + gr;
            bv[0] = Vt[d * 36 + k2 * 8 + gc];
            bv[1] = Vt[d * 36 + k2 * 8 + gc + 4];
            mma_bf16(o[0][ntd], pf[0], bv);
            mma_bf16(o[1][ntd], pf[1], bv);
        }
    }

    // ---- scale rows by 1/sum and store bf16 ----
#pragma unroll
    for (int mt = 0; mt < 2; ++mt) {
#pragma unroll
        for (int hf = 0; hf < 2; ++hf) {
            int row = qb + mt * 16 + gr + hf * 8;
            if (row < Nn) {
                float iv = invr[mt][hf];
                bf16* op = g_ATT + ((size_t)(win * Nn + row)) * Cc + h * HDd;
#pragma unroll
                for (int ntd = 0; ntd < 4; ++ntd) {
                    *(uint32_t*)(op + ntd * 8 + 2 * gc) =
                        packbf(o[mt][ntd][hf * 2] * iv, o[mt][ntd][hf * 2 + 1] * iv);
                }
            }
        }
    }
}

// --------------------------- launch ------------------------------------------
extern "C" void kernel_launch(void* const* d_in, const int* in_sizes, int n_in,
                              void* d_out, int out_size) {
    const float* x        = (const float*)d_in[0];
    const float* norm1_g  = (const float*)d_in[1];
    const float* norm1_b  = (const float*)d_in[2];
    const float* qkv_w    = (const float*)d_in[3];
    const float* rel_bias = (const float*)d_in[4];
    const float* proj_w   = (const float*)d_in[5];
    const float* proj_b   = (const float*)d_in[6];
    const float* norm2_g  = (const float*)d_in[7];
    const float* norm2_b  = (const float*)d_in[8];
    const float* fc1_w    = (const float*)d_in[9];
    const float* fc1_b    = (const float*)d_in[10];
    const float* fc2_w    = (const float*)d_in[11];
    const float* fc2_b    = (const float*)d_in[12];
    float* out = (float*)d_out;

    bf16 *XW, *QKV, *ATT, *XN2, *Hb, *Wq, *Wp, *W1, *W2;
    float *XR;
    cudaGetSymbolAddress((void**)&XW,  g_XW);
    cudaGetSymbolAddress((void**)&QKV, g_QKV);
    cudaGetSymbolAddress((void**)&ATT, g_ATT);
    cudaGetSymbolAddress((void**)&XR,  g_XR);
    cudaGetSymbolAddress((void**)&XN2, g_XN2);
    cudaGetSymbolAddress((void**)&Hb,  g_H);
    cudaGetSymbolAddress((void**)&Wq,  g_Wq);
    cudaGetSymbolAddress((void**)&Wp,  g_Wp);
    cudaGetSymbolAddress((void**)&W1,  g_W1);
    cudaGetSymbolAddress((void**)&W2,  g_W2);

    cudaFuncSetAttribute(gemm_mma<0, 192>, cudaFuncAttributeMaxDynamicSharedMemorySize, SMEM_BYTES);
    cudaFuncSetAttribute(gemm_mma<1, 192>, cudaFuncAttributeMaxDynamicSharedMemorySize, SMEM_BYTES);
    cudaFuncSetAttribute(gemm_mma<2, 192>, cudaFuncAttributeMaxDynamicSharedMemorySize, SMEM_BYTES);
    cudaFuncSetAttribute(gemm_mma<3, 768>, cudaFuncAttributeMaxDynamicSharedMemorySize, SMEM_BYTES);
    cudaFuncSetAttribute(attn_mma_kernel, cudaFuncAttributeMaxDynamicSharedMemorySize, ATTN_SMEM_BYTES);

    // 0. weights -> bf16; bias+mask table
    wconv_kernel<<<(MLPH * Cc + 255) / 256, 256>>>(qkv_w, proj_w, fc1_w, fc2_w);
    bm_init_kernel<<<(4 * NHh * 64 * 64 + 255) / 256, 256>>>(rel_bias);
    // 1. LN1 + cyclic shift + window partition -> XW (bf16)
    ln1_gather_kernel<<<TOT / 8, 256>>>(x, norm1_g, norm1_b);
    // 2. QKV gemm -> QKV (bf16)
    gemm_mma<0, 192><<<dim3(TOT / BM, 576 / BN), 256, SMEM_BYTES>>>(XW, Wq, nullptr, nullptr, QKV, 3 * Cc);
    // 3. windowed attention (mma) -> ATT (bf16)
    attn_mma_kernel<<<NWIN, 384, ATTN_SMEM_BYTES>>>();
    // 4. proj + bias + reverse scatter + residual -> XR (fp32)
    gemm_mma<1, 192><<<dim3(TOT / BM, Cc / BN), 256, SMEM_BYTES>>>(ATT, Wp, proj_b, x, XR, Cc);
    // 5. LN2 -> XN2 (bf16)
    ln2_kernel<<<TOT / 8, 256>>>(norm2_g, norm2_b);
    // 6. FC1 + bias + exact GELU -> H (bf16)
    gemm_mma<2, 192><<<dim3(TOT / BM, MLPH / BN), 256, SMEM_BYTES>>>(XN2, W1, fc1_b, nullptr, Hb, MLPH);
    // 7. FC2 + bias + residual(XR) -> out (fp32)
    gemm_mma<3, 768><<<dim3(TOT / BM, Cc / BN), 256, SMEM_BYTES>>>(Hb, W2, fc2_b, XR, out, Cc);
}

// round 9
// speedup vs baseline: 4.7790x; 1.1468x over previous
#include <cuda_runtime.h>
#include <cuda_bf16.h>
#include <math.h>
#include <stdint.h>

// ---------------------------------------------------------------------------
// Swin block: B=32,H=W=56,C=192,NH=6,WS=7,SS=3,HD=32,N=49,MLP_H=768
// GEMMs + attention via mma.sync m16n8k16 bf16, ldmatrix fragment loads.
// ---------------------------------------------------------------------------

#define Bn     32
#define Hh     56
#define Ww     56
#define Cc     192
#define NHh    6
#define WSs    7
#define SSs    3
#define HDd    32
#define Nn     49
#define MLPH   768
#define Ltok   (Hh*Ww)
#define TOT    (Bn*Ltok)          // 100352
#define NWIN   2048
#define SCALEF 0.17677669529663687f

// GEMM tiling: CTA 128x64, K-chunk 64, 8 warps (4M x 2N), warp tile 32x32.
#define BM   128
#define BN   64
#define BK   64
#define PADE 72                   // row pitch in bf16 (144B)
#define ABUFE (BM*PADE)           // 9216
#define BBUFE (BN*PADE)           // 4608
#define SMEM_BYTES ((2*ABUFE + 2*BBUFE) * 2)   // 55296

typedef __nv_bfloat16 bf16;
typedef __nv_bfloat162 bf162;

// ------------------------- scratch (device globals) ------------------------
__device__ bf16  g_XW [TOT * Cc];
__device__ bf16  g_QKV[TOT * 3 * Cc];
__device__ bf16  g_ATT[TOT * Cc];
__device__ float g_XR [TOT * Cc];
__device__ bf16  g_XN2[TOT * Cc];
__device__ bf16  g_H  [TOT * MLPH];
__device__ bf16  g_Wq [576 * Cc];
__device__ bf16  g_Wp [Cc * Cc];
__device__ bf16  g_W1 [MLPH * Cc];
__device__ bf16  g_W2 [Cc * MLPH];
__device__ float g_BM [4 * NHh * 64 * 64];

// --------------------------- PTX helpers -----------------------------------
__device__ __forceinline__ uint32_t smem_u32(const void* p) {
    uint32_t a;
    asm("{ .reg .u64 t; cvta.to.shared.u64 t, %1; cvt.u32.u64 %0, t; }"
        : "=r"(a) : "l"(p));
    return a;
}

#define CP_ASYNC16(dst, src) \
    asm volatile("cp.async.cg.shared.global [%0], [%1], 16;" :: "r"(dst), "l"(src))
#define CP_COMMIT() asm volatile("cp.async.commit_group;")
#define CP_WAIT(n)  asm volatile("cp.async.wait_group %0;" :: "n"(n))

__device__ __forceinline__ void mma_bf16(float* c, const uint32_t* a, const uint32_t* b) {
    asm volatile(
        "mma.sync.aligned.m16n8k16.row.col.f32.bf16.bf16.f32 "
        "{%0,%1,%2,%3}, {%4,%5,%6,%7}, {%8,%9}, {%0,%1,%2,%3};"
        : "+f"(c[0]), "+f"(c[1]), "+f"(c[2]), "+f"(c[3])
        : "r"(a[0]), "r"(a[1]), "r"(a[2]), "r"(a[3]), "r"(b[0]), "r"(b[1]));
}

__device__ __forceinline__ void ldsm_x4(uint32_t* r, uint32_t addr) {
    asm volatile("ldmatrix.sync.aligned.m8n8.x4.shared.b16 {%0,%1,%2,%3}, [%4];"
                 : "=r"(r[0]), "=r"(r[1]), "=r"(r[2]), "=r"(r[3]) : "r"(addr));
}

__device__ __forceinline__ uint32_t packbf(float lo, float hi) {
    uint32_t r;
    asm("cvt.rn.bf16x2.f32 %0, %1, %2;" : "=r"(r) : "f"(hi), "f"(lo));
    return r;
}

// --------------------- token <-> (shifted window) mapping ------------------
__device__ __forceinline__ int win_to_tok(int t) {
    int win = t / Nn, r = t - win * Nn;
    int b = win >> 6, w_ = win & 63;
    int wh = w_ >> 3, ww = w_ & 7;
    int ih = r / WSs, iw = r - ih * WSs;
    int rr = wh * WSs + ih + SSs; if (rr >= Hh) rr -= Hh;
    int cc = ww * WSs + iw + SSs; if (cc >= Ww) cc -= Ww;
    return b * Ltok + rr * Ww + cc;
}

// ----------------------- weight conversion to bf16 --------------------------
__global__ void wconv_kernel(const float* __restrict__ qw, const float* __restrict__ pw,
                             const float* __restrict__ w1, const float* __restrict__ w2) {
    int i = blockIdx.x * blockDim.x + threadIdx.x;
    if (i < 576 * Cc)  g_Wq[i] = __float2bfloat16(qw[i]);
    if (i < Cc * Cc)   g_Wp[i] = __float2bfloat16(pw[i]);
    if (i < MLPH * Cc) g_W1[i] = __float2bfloat16(w1[i]);
    if (i < Cc * MLPH) g_W2[i] = __float2bfloat16(w2[i]);
}

// -------------------- bias + shift-mask table init -------------------------
__global__ void bm_init_kernel(const float* __restrict__ tbl) {
    int idx = blockIdx.x * blockDim.x + threadIdx.x;
    if (idx >= 4 * NHh * 64 * 64) return;
    int j = idx & 63, i = (idx >> 6) & 63;
    int hh = (idx >> 12) % NHh, wt = (idx >> 12) / NHh;
    float v;
    if (i < Nn && j < Nn) {
        int ih = i / 7, iw = i % 7, jh = j / 7, jw = j % 7;
        int ridx = (ih - jh + 6) * 13 + (iw - jw + 6);
        v = tbl[ridx * NHh + hh];
        int th = wt >> 1, tw = wt & 1;
        int li = (th ? (ih < 4 ? 1 : 2) : 0) * 3 + (tw ? (iw < 4 ? 1 : 2) : 0);
        int lj = (th ? (jh < 4 ? 1 : 2) : 0) * 3 + (tw ? (jw < 4 ? 1 : 2) : 0);
        if (li != lj) v -= 100.f;
    } else {
        v = -1e30f;
    }
    g_BM[idx] = v;
}

// --------------------------- LN kernels -------------------------------------
__global__ void ln1_gather_kernel(const float* __restrict__ x,
                                  const float* __restrict__ g,
                                  const float* __restrict__ bt) {
    int warp = (blockIdx.x * blockDim.x + threadIdx.x) >> 5;
    int lane = threadIdx.x & 31;
    if (warp >= TOT) return;
    const float* src = x + (size_t)win_to_tok(warp) * Cc;
    float v[6], s = 0.f, ss = 0.f;
#pragma unroll
    for (int k = 0; k < 6; k++) { v[k] = src[lane + k * 32]; s += v[k]; ss += v[k] * v[k]; }
#pragma unroll
    for (int o = 16; o; o >>= 1) {
        s  += __shfl_xor_sync(0xffffffffu, s, o);
        ss += __shfl_xor_sync(0xffffffffu, ss, o);
    }
    float mu = s * (1.f / Cc);
    float rstd = rsqrtf(ss * (1.f / Cc) - mu * mu + 1e-5f);
    bf16* dst = g_XW + (size_t)warp * Cc;
#pragma unroll
    for (int k = 0; k < 6; k++) {
        int c = lane + k * 32;
        dst[c] = __float2bfloat16((v[k] - mu) * rstd * g[c] + bt[c]);
    }
}

__global__ void ln2_kernel(const float* __restrict__ g,
                           const float* __restrict__ bt) {
    int warp = (blockIdx.x * blockDim.x + threadIdx.x) >> 5;
    int lane = threadIdx.x & 31;
    if (warp >= TOT) return;
    const float* src = g_XR + (size_t)warp * Cc;
    float v[6], s = 0.f, ss = 0.f;
#pragma unroll
    for (int k = 0; k < 6; k++) { v[k] = src[lane + k * 32]; s += v[k]; ss += v[k] * v[k]; }
#pragma unroll
    for (int o = 16; o; o >>= 1) {
        s  += __shfl_xor_sync(0xffffffffu, s, o);
        ss += __shfl_xor_sync(0xffffffffu, ss, o);
    }
    float mu = s * (1.f / Cc);
    float rstd = rsqrtf(ss * (1.f / Cc) - mu * mu + 1e-5f);
    bf16* dst = g_XN2 + (size_t)warp * Cc;
#pragma unroll
    for (int k = 0; k < 6; k++) {
        int c = lane + k * 32;
        dst[c] = __float2bfloat16((v[k] - mu) * rstd * g[c] + bt[c]);
    }
}

// --------------------------- bf16 mma GEMM ----------------------------------
// C[M,Nd] = A[M,KK] * W[Nd,KK]^T.  CTA 128x64, 8 warps 4(M)x2(N), warp 32x32.
// ldmatrix.x4 fragment loads; cp.async double-buffered K-chunks of 64.
template <int EPI, int KK>
__global__ __launch_bounds__(256)
void gemm_mma(const bf16* __restrict__ A, const bf16* __restrict__ W,
              const float* __restrict__ bias, const float* __restrict__ res,
              void* __restrict__ outp, int Nd) {
    constexpr int NC = KK / BK;
    extern __shared__ __align__(16) bf16 smem[];
    const uint32_t as_u[2] = {smem_u32(smem), smem_u32(smem + ABUFE)};
    const uint32_t bs_u[2] = {smem_u32(smem + 2 * ABUFE), smem_u32(smem + 2 * ABUFE + BBUFE)};

    const int tid = threadIdx.x;
    const int wid = tid >> 5;
    const int lane = tid & 31;
    const int gr = lane >> 2, gc = lane & 3;
    const int wm = wid >> 1;          // 0..3
    const int wn = wid & 1;           // 0..1
    const int mbase = blockIdx.x * BM;
    const int nbase = blockIdx.y * BN;

    const bf16* Ab = A + (size_t)mbase * KK;
    const bf16* Wb = W + (size_t)nbase * KK;

    // ldmatrix per-lane source rows/cols
    const int rowA = wm * 32 + (lane & 15);
    const int colA = (lane >> 4) << 3;
    const int rowB = wn * 32 + (lane & 7) + ((lane >> 4) << 3);
    const int colB = ((lane >> 3) & 1) << 3;

    float acc[2][4][4];
#pragma unroll
    for (int i = 0; i < 2; i++)
#pragma unroll
        for (int j = 0; j < 4; j++)
#pragma unroll
            for (int k = 0; k < 4; k++) acc[i][j][k] = 0.f;

    // prologue: chunk 0
#pragma unroll
    for (int i = tid; i < BM * 8; i += 256) {
        int row = i >> 3, seg = i & 7;
        CP_ASYNC16(as_u[0] + (uint32_t)(row * 144 + seg * 16),
                   Ab + (size_t)row * KK + seg * 8);
    }
#pragma unroll
    for (int i = tid; i < BN * 8; i += 256) {
        int row = i >> 3, seg = i & 7;
        CP_ASYNC16(bs_u[0] + (uint32_t)(row * 144 + seg * 16),
                   Wb + (size_t)row * KK + seg * 8);
    }
    CP_COMMIT();

    for (int c = 0; c < NC; ++c) {
        if (c + 1 < NC) {
            const int nb = (c + 1) & 1;
            const int ko = (c + 1) * BK;
#pragma unroll
            for (int i = tid; i < BM * 8; i += 256) {
                int row = i >> 3, seg = i & 7;
                CP_ASYNC16(as_u[nb] + (uint32_t)(row * 144 + seg * 16),
                           Ab + (size_t)row * KK + ko + seg * 8);
            }
#pragma unroll
            for (int i = tid; i < BN * 8; i += 256) {
                int row = i >> 3, seg = i & 7;
                CP_ASYNC16(bs_u[nb] + (uint32_t)(row * 144 + seg * 16),
                           Wb + (size_t)row * KK + ko + seg * 8);
            }
            CP_COMMIT();
            CP_WAIT(1);
        } else {
            CP_WAIT(0);
        }
        __syncthreads();

        const uint32_t ab = as_u[c & 1];
        const uint32_t bb = bs_u[c & 1];
#pragma unroll
        for (int ks = 0; ks < 4; ++ks) {
            const int kk = ks * 16;
            uint32_t af[2][4], bq[2][4];
            ldsm_x4(af[0], ab + (uint32_t)(rowA * PADE + kk + colA) * 2);
            ldsm_x4(af[1], ab + (uint32_t)((rowA + 16) * PADE + kk + colA) * 2);
            ldsm_x4(bq[0], bb + (uint32_t)(rowB * PADE + kk + colB) * 2);
            ldsm_x4(bq[1], bb + (uint32_t)((rowB + 16) * PADE + kk + colB) * 2);
#pragma unroll
            for (int mt = 0; mt < 2; ++mt) {
                mma_bf16(acc[mt][0], af[mt], &bq[0][0]);
                mma_bf16(acc[mt][1], af[mt], &bq[0][2]);
                mma_bf16(acc[mt][2], af[mt], &bq[1][0]);
                mma_bf16(acc[mt][3], af[mt], &bq[1][2]);
            }
        }
        __syncthreads();
    }

    // ----------------------- fused epilogue ---------------------------------
#pragma unroll
    for (int mt = 0; mt < 2; ++mt) {
#pragma unroll
        for (int half = 0; half < 2; ++half) {
            int row = mbase + wm * 32 + mt * 16 + gr + half * 8;
            int orow = row;
            if (EPI == 1) orow = win_to_tok(row);
#pragma unroll
            for (int nt = 0; nt < 4; ++nt) {
                int col = nbase + wn * 32 + nt * 8 + gc * 2;
                float v0 = acc[mt][nt][half * 2 + 0];
                float v1 = acc[mt][nt][half * 2 + 1];
                if (EPI == 0) {
                    *(uint32_t*)((bf16*)outp + (size_t)orow * Nd + col) = packbf(v0, v1);
                } else if (EPI == 1) {
                    const float* rp = res + (size_t)orow * Nd + col;
                    float2 o = make_float2(v0 + bias[col] + rp[0],
                                           v1 + bias[col + 1] + rp[1]);
                    *(float2*)((float*)outp + (size_t)orow * Nd + col) = o;
                } else if (EPI == 2) {
                    float a0 = v0 + bias[col], a1 = v1 + bias[col + 1];
                    const float kc = 0.70710678118654752f;
                    *(uint32_t*)((bf16*)outp + (size_t)orow * Nd + col) =
                        packbf(0.5f * a0 * (1.f + erff(a0 * kc)),
                               0.5f * a1 * (1.f + erff(a1 * kc)));
                } else {
                    const float* rp = res + (size_t)row * Nd + col;
                    float2 o = make_float2(v0 + bias[col] + rp[0],
                                           v1 + bias[col + 1] + rp[1]);
                    *(float2*)((float*)outp + (size_t)orow * Nd + col) = o;
                }
            }
        }
    }
}

// --------------------------- mma attention ----------------------------------
#define ATTN_SMEM_BYTES (6 * 3712 * 4)   // 89088

__global__ __launch_bounds__(384, 1)
void attn_mma_kernel() {
    extern __shared__ uint32_t sm32[];
    const int tid = threadIdx.x;
    const int win = blockIdx.x;
    const int h = tid >> 6;
    const int t2 = tid & 63;

    uint32_t* Qs = sm32 + h * 3712;
    uint32_t* Ks = Qs + 1280;
    uint32_t* Vt = Ks + 1280;

    for (int i = t2; i < 3712; i += 64) Qs[i] = 0;
    __syncthreads();

    const uint32_t* qkv = (const uint32_t*)g_QKV + (size_t)win * Nn * 288;
    bf16* vtb = (bf16*)Vt;
    for (int i = t2; i < Nn * 16; i += 64) {
        int row = i >> 4, wd = i & 15;
        const uint32_t* tp = qkv + row * 288 + h * 16 + wd;
        Qs[row * 20 + wd] = tp[0];
        Ks[row * 20 + wd] = tp[96];
        uint32_t vv = tp[192];
        bf162 v2 = *(bf162*)&vv;
        vtb[(2 * wd) * 72 + row]     = v2.x;
        vtb[(2 * wd + 1) * 72 + row] = v2.y;
    }
    __syncthreads();

    const int w = tid >> 5;
    const int lane = tid & 31;
    const int gr = lane >> 2, gc = lane & 3;
    const int qb = (w & 1) * 32;
    const int wh = (win & 63) >> 3, ww = win & 7;
    const int wt = ((wh == 7) ? 2 : 0) + ((ww == 7) ? 1 : 0);
    const float* bmp = g_BM + ((size_t)(wt * NHh + h) << 12);

    float sacc[2][8][4];
#pragma unroll
    for (int a = 0; a < 2; a++)
#pragma unroll
        for (int b = 0; b < 8; b++)
#pragma unroll
            for (int cse = 0; cse < 4; cse++) sacc[a][b][cse] = 0.f;

#pragma unroll
    for (int kst = 0; kst < 2; ++kst) {
        uint32_t af[2][4], bfr[8][2];
#pragma unroll
        for (int mt = 0; mt < 2; ++mt) {
            int r = qb + mt * 16 + gr;
            af[mt][0] = Qs[r * 20 + kst * 8 + gc];
            af[mt][1] = Qs[(r + 8) * 20 + kst * 8 + gc];
            af[mt][2] = Qs[r * 20 + kst * 8 + gc + 4];
            af[mt][3] = Qs[(r + 8) * 20 + kst * 8 + gc + 4];
        }
#pragma unroll
        for (int nt = 0; nt < 8; ++nt) {
            int j = nt * 8 + gr;
            bfr[nt][0] = Ks[j * 20 + kst * 8 + gc];
            bfr[nt][1] = Ks[j * 20 + kst * 8 + gc + 4];
        }
#pragma unroll
        for (int mt = 0; mt < 2; ++mt)
#pragma unroll
            for (int nt = 0; nt < 8; ++nt)
                mma_bf16(sacc[mt][nt], af[mt], bfr[nt]);
    }

    float invr[2][2];
#pragma unroll
    for (int mt = 0; mt < 2; ++mt) {
#pragma unroll
        for (int hf = 0; hf < 2; ++hf) {
            int row = qb + mt * 16 + gr + hf * 8;
            const float* bmr = bmp + row * 64 + 2 * gc;
            float v[8][2], mx = -3e38f;
#pragma unroll
            for (int nt = 0; nt < 8; ++nt) {
                float2 bm2 = *(const float2*)(bmr + nt * 8);
                v[nt][0] = sacc[mt][nt][hf * 2 + 0] * SCALEF + bm2.x;
                v[nt][1] = sacc[mt][nt][hf * 2 + 1] * SCALEF + bm2.y;
                mx = fmaxf(mx, fmaxf(v[nt][0], v[nt][1]));
            }
            mx = fmaxf(mx, __shfl_xor_sync(0xffffffffu, mx, 1));
            mx = fmaxf(mx, __shfl_xor_sync(0xffffffffu, mx, 2));
            float sum = 0.f;
#pragma unroll
            for (int nt = 0; nt < 8; ++nt) {
                float e0 = __expf(v[nt][0] - mx);
                float e1 = __expf(v[nt][1] - mx);
                sacc[mt][nt][hf * 2 + 0] = e0;
                sacc[mt][nt][hf * 2 + 1] = e1;
                sum += e0 + e1;
            }
            sum += __shfl_xor_sync(0xffffffffu, sum, 1);
            sum += __shfl_xor_sync(0xffffffffu, sum, 2);
            invr[mt][hf] = 1.f / sum;
        }
    }

    float o[2][4][4];
#pragma unroll
    for (int a = 0; a < 2; a++)
#pragma unroll
        for (int b = 0; b < 4; b++)
#pragma unroll
            for (int cse = 0; cse < 4; cse++) o[a][b][cse] = 0.f;

#pragma unroll
    for (int k2 = 0; k2 < 4; ++k2) {
        uint32_t pf[2][4];
#pragma unroll
        for (int mt = 0; mt < 2; ++mt) {
            pf[mt][0] = packbf(sacc[mt][2 * k2][0],     sacc[mt][2 * k2][1]);
            pf[mt][1] = packbf(sacc[mt][2 * k2][2],     sacc[mt][2 * k2][3]);
            pf[mt][2] = packbf(sacc[mt][2 * k2 + 1][0], sacc[mt][2 * k2 + 1][1]);
            pf[mt][3] = packbf(sacc[mt][2 * k2 + 1][2], sacc[mt][2 * k2 + 1][3]);
        }
#pragma unroll
        for (int ntd = 0; ntd < 4; ++ntd) {
            uint32_t bv[2];
            int d = ntd * 8 + gr;
            bv[0] = Vt[d * 36 + k2 * 8 + gc];
            bv[1] = Vt[d * 36 + k2 * 8 + gc + 4];
            mma_bf16(o[0][ntd], pf[0], bv);
            mma_bf16(o[1][ntd], pf[1], bv);
        }
    }

#pragma unroll
    for (int mt = 0; mt < 2; ++mt) {
#pragma unroll
        for (int hf = 0; hf < 2; ++hf) {
            int row = qb + mt * 16 + gr + hf * 8;
            if (row < Nn) {
                float iv = invr[mt][hf];
                bf16* op = g_ATT + ((size_t)(win * Nn + row)) * Cc + h * HDd;
#pragma unroll
                for (int ntd = 0; ntd < 4; ++ntd) {
                    *(uint32_t*)(op + ntd * 8 + 2 * gc) =
                        packbf(o[mt][ntd][hf * 2] * iv, o[mt][ntd][hf * 2 + 1] * iv);
                }
            }
        }
    }
}

// --------------------------- launch ------------------------------------------
extern "C" void kernel_launch(void* const* d_in, const int* in_sizes, int n_in,
                              void* d_out, int out_size) {
    const float* x        = (const float*)d_in[0];
    const float* norm1_g  = (const float*)d_in[1];
    const float* norm1_b  = (const float*)d_in[2];
    const float* qkv_w    = (const float*)d_in[3];
    const float* rel_bias = (const float*)d_in[4];
    const float* proj_w   = (const float*)d_in[5];
    const float* proj_b   = (const float*)d_in[6];
    const float* norm2_g  = (const float*)d_in[7];
    const float* norm2_b  = (const float*)d_in[8];
    const float* fc1_w    = (const float*)d_in[9];
    const float* fc1_b    = (const float*)d_in[10];
    const float* fc2_w    = (const float*)d_in[11];
    const float* fc2_b    = (const float*)d_in[12];
    float* out = (float*)d_out;

    bf16 *XW, *QKV, *ATT, *XN2, *Hb, *Wq, *Wp, *W1, *W2;
    float *XR;
    cudaGetSymbolAddress((void**)&XW,  g_XW);
    cudaGetSymbolAddress((void**)&QKV, g_QKV);
    cudaGetSymbolAddress((void**)&ATT, g_ATT);
    cudaGetSymbolAddress((void**)&XR,  g_XR);
    cudaGetSymbolAddress((void**)&XN2, g_XN2);
    cudaGetSymbolAddress((void**)&Hb,  g_H);
    cudaGetSymbolAddress((void**)&Wq,  g_Wq);
    cudaGetSymbolAddress((void**)&Wp,  g_Wp);
    cudaGetSymbolAddress((void**)&W1,  g_W1);
    cudaGetSymbolAddress((void**)&W2,  g_W2);

    cudaFuncSetAttribute(gemm_mma<0, 192>, cudaFuncAttributeMaxDynamicSharedMemorySize, SMEM_BYTES);
    cudaFuncSetAttribute(gemm_mma<1, 192>, cudaFuncAttributeMaxDynamicSharedMemorySize, SMEM_BYTES);
    cudaFuncSetAttribute(gemm_mma<2, 192>, cudaFuncAttributeMaxDynamicSharedMemorySize, SMEM_BYTES);
    cudaFuncSetAttribute(gemm_mma<3, 768>, cudaFuncAttributeMaxDynamicSharedMemorySize, SMEM_BYTES);
    cudaFuncSetAttribute(attn_mma_kernel, cudaFuncAttributeMaxDynamicSharedMemorySize, ATTN_SMEM_BYTES);

    // 0. weights -> bf16; bias+mask table
    wconv_kernel<<<(MLPH * Cc + 255) / 256, 256>>>(qkv_w, proj_w, fc1_w, fc2_w);
    bm_init_kernel<<<(4 * NHh * 64 * 64 + 255) / 256, 256>>>(rel_bias);
    // 1. LN1 + cyclic shift + window partition -> XW (bf16)
    ln1_gather_kernel<<<TOT / 8, 256>>>(x, norm1_g, norm1_b);
    // 2. QKV gemm -> QKV (bf16)
    gemm_mma<0, 192><<<dim3(TOT / BM, 576 / BN), 256, SMEM_BYTES>>>(XW, Wq, nullptr, nullptr, QKV, 3 * Cc);
    // 3. windowed attention (mma) -> ATT (bf16)
    attn_mma_kernel<<<NWIN, 384, ATTN_SMEM_BYTES>>>();
    // 4. proj + bias + reverse scatter + residual -> XR (fp32)
    gemm_mma<1, 192><<<dim3(TOT / BM, Cc / BN), 256, SMEM_BYTES>>>(ATT, Wp, proj_b, x, XR, Cc);
    // 5. LN2 -> XN2 (bf16)
    ln2_kernel<<<TOT / 8, 256>>>(norm2_g, norm2_b);
    // 6. FC1 + bias + exact GELU -> H (bf16)
    gemm_mma<2, 192><<<dim3(TOT / BM, MLPH / BN), 256, SMEM_BYTES>>>(XN2, W1, fc1_b, nullptr, Hb, MLPH);
    // 7. FC2 + bias + residual(XR) -> out (fp32)
    gemm_mma<3, 768><<<dim3(TOT / BM, Cc / BN), 256, SMEM_BYTES>>>(Hb, W2, fc2_b, XR, out, Cc);
}